// round 1
// baseline (speedup 1.0000x reference)
#include <cuda_runtime.h>
#include <cstddef>

#define NNODES 20000
#define HID    512
#define NEDGE  160000
#define NTYPES 5
#define NET    6
#define FIN    64

// -------- scratch (static __device__ arrays; no allocs allowed) --------
__device__ float g_h  [NTYPES * NNODES * HID];   // 204.8 MB
__device__ float g_out[NTYPES * NNODES * HID];   // 204.8 MB
__device__ float g_agg[NNODES * HID];            // 41 MB
__device__ float g_mid[NNODES * HID];            // 41 MB

// ---------------------------------------------------------------------
// SGEMM: C[M][512] = act(A[M][K] @ W[K][512] + bias)  (+= existing C if ACCUM)
// Block tile 128x128, BK=8, 256 threads, 8x8 accumulators per thread.
// ---------------------------------------------------------------------
template<int RELU, int ACCUM>
__global__ __launch_bounds__(256, 2)
void sgemm512(const float* __restrict__ A, const float* __restrict__ W,
              const float* __restrict__ bias, float* __restrict__ C,
              int M, int K)
{
    __shared__ float As[8][132];   // padded: kills 2-way STS bank conflict
    __shared__ float Bs[8][128];

    const int bm  = blockIdx.x * 128;
    const int bn  = blockIdx.y * 128;
    const int tid = threadIdx.x;
    const int tx  = tid & 15;      // 16 col-threads
    const int ty  = tid >> 4;      // 16 row-threads

    // global-load mapping
    const int a_row = tid >> 1;          // 0..127
    const int a_col = (tid & 1) * 4;     // 0 or 4
    const int b_row = tid >> 5;          // 0..7
    const int b_col = (tid & 31) * 4;    // 0..124

    float acc[8][8];
#pragma unroll
    for (int i = 0; i < 8; i++)
#pragma unroll
        for (int j = 0; j < 8; j++) acc[i][j] = 0.f;

    const int gr = bm + a_row;
    const float* Aptr = A + (size_t)gr * K + a_col;
    const float* Wptr = W + (size_t)b_row * HID + bn + b_col;

    for (int k0 = 0; k0 < K; k0 += 8) {
        float4 av = make_float4(0.f, 0.f, 0.f, 0.f);
        if (gr < M) av = *(const float4*)(Aptr + k0);
        As[a_col + 0][a_row] = av.x;
        As[a_col + 1][a_row] = av.y;
        As[a_col + 2][a_row] = av.z;
        As[a_col + 3][a_row] = av.w;

        *(float4*)&Bs[b_row][b_col] = *(const float4*)(Wptr + (size_t)k0 * HID);
        __syncthreads();

#pragma unroll
        for (int k = 0; k < 8; k++) {
            float a[8], b[8];
            *(float4*)&a[0] = *(const float4*)&As[k][ty * 4];
            *(float4*)&a[4] = *(const float4*)&As[k][64 + ty * 4];
            *(float4*)&b[0] = *(const float4*)&Bs[k][tx * 4];
            *(float4*)&b[4] = *(const float4*)&Bs[k][64 + tx * 4];
#pragma unroll
            for (int i = 0; i < 8; i++)
#pragma unroll
                for (int j = 0; j < 8; j++)
                    acc[i][j] = fmaf(a[i], b[j], acc[i][j]);
        }
        __syncthreads();
    }

    // epilogue
#pragma unroll
    for (int ii = 0; ii < 2; ii++) {
#pragma unroll
        for (int i2 = 0; i2 < 4; i2++) {
            int r = bm + ii * 64 + ty * 4 + i2;
            if (r >= M) continue;
#pragma unroll
            for (int jj = 0; jj < 2; jj++) {
                int c = bn + jj * 64 + tx * 4;
                float4 bb = *(const float4*)(bias + c);
                float4 v;
                v.x = acc[ii * 4 + i2][jj * 4 + 0] + bb.x;
                v.y = acc[ii * 4 + i2][jj * 4 + 1] + bb.y;
                v.z = acc[ii * 4 + i2][jj * 4 + 2] + bb.z;
                v.w = acc[ii * 4 + i2][jj * 4 + 3] + bb.w;
                if (RELU) {
                    v.x = fmaxf(v.x, 0.f); v.y = fmaxf(v.y, 0.f);
                    v.z = fmaxf(v.z, 0.f); v.w = fmaxf(v.w, 0.f);
                }
                float* cp = C + (size_t)r * HID + c;
                if (ACCUM) {
                    float4 o = *(const float4*)cp;
                    v.x += o.x; v.y += o.y; v.z += o.z; v.w += o.w;
                }
                *(float4*)cp = v;
            }
        }
    }
}

// ---------------------------------------------------------------------
// Edge scatter: agg[dst[e]] += h_src[src[e]]  (agg pre-initialized with h_dst)
// One 128-thread block per edge; vector reductions (red.global.add.v4.f32).
// ---------------------------------------------------------------------
__global__ void scatter_add_kernel(const float* __restrict__ hsrc,
                                   const int* __restrict__ srcI,
                                   const int* __restrict__ dstI,
                                   float* __restrict__ agg)
{
    const int e  = blockIdx.x;
    const int s  = srcI[e];
    const int d  = dstI[e];
    const int t4 = threadIdx.x * 4;
    float4 v = *(const float4*)(hsrc + (size_t)s * HID + t4);
    float* p = agg + (size_t)d * HID + t4;
    asm volatile("red.global.add.v4.f32 [%0], {%1, %2, %3, %4};"
                 :: "l"(p), "f"(v.x), "f"(v.y), "f"(v.z), "f"(v.w)
                 : "memory");
}

// ---------------------------------------------------------------------
__global__ void relu_kernel(const float* __restrict__ in, float* __restrict__ out, int n4)
{
    int i = blockIdx.x * blockDim.x + threadIdx.x;
    int stride = gridDim.x * blockDim.x;
    for (; i < n4; i += stride) {
        float4 v = ((const float4*)in)[i];
        v.x = fmaxf(v.x, 0.f);
        v.y = fmaxf(v.y, 0.f);
        v.z = fmaxf(v.z, 0.f);
        v.w = fmaxf(v.w, 0.f);
        ((float4*)out)[i] = v;
    }
}

// ---------------------------------------------------------------------
// Output head: out[i] = dot(h0[i], W_out) + b_out    (one warp per row)
// ---------------------------------------------------------------------
__global__ void head_kernel(const float* __restrict__ h0, const float* __restrict__ Wout,
                            const float* __restrict__ bout, float* __restrict__ out, int M)
{
    const int gw   = (int)((blockIdx.x * (size_t)blockDim.x + threadIdx.x) >> 5);
    const int lane = threadIdx.x & 31;
    if (gw >= M) return;
    const float* row = h0 + (size_t)gw * HID;
    float s = 0.f;
#pragma unroll
    for (int i = 0; i < 4; i++) {
        int c = (lane + i * 32) * 4;
        float4 a = *(const float4*)(row + c);
        float4 w = *(const float4*)(Wout + c);
        s += a.x * w.x + a.y * w.y + a.z * w.z + a.w * w.w;
    }
#pragma unroll
    for (int o = 16; o; o >>= 1) s += __shfl_xor_sync(0xffffffffu, s, o);
    if (lane == 0) out[gw] = s + bout[0];
}

// ---------------------------------------------------------------------
extern "C" void kernel_launch(void* const* d_in, const int* in_sizes, int n_in,
                              void* d_out, int out_size)
{
    const float* x_all  = (const float*)d_in[0];   // [5,N,64]
    const float* W_in   = (const float*)d_in[1];   // [5,64,512]
    const float* b_in   = (const float*)d_in[2];   // [5,512]
    const float* W1     = (const float*)d_in[3];   // [2,6,512,512]
    const float* b1     = (const float*)d_in[4];   // [2,6,512]
    const float* W2     = (const float*)d_in[5];   // [2,6,512,512]
    const float* b2     = (const float*)d_in[6];   // [2,6,512]
    const float* W_out  = (const float*)d_in[7];   // [512,1]
    const float* b_out  = (const float*)d_in[8];   // [1]
    const int*   edges  = (const int*)d_in[9];     // [6,2,E]
    float* out = (float*)d_out;

    float *h, *outb, *agg, *mid;
    cudaGetSymbolAddress((void**)&h,    g_h);
    cudaGetSymbolAddress((void**)&outb, g_out);
    cudaGetSymbolAddress((void**)&agg,  g_agg);
    cudaGetSymbolAddress((void**)&mid,  g_mid);

    const dim3 gg((NNODES + 127) / 128, HID / 128);

    // 1) input projection per node type: h = relu(x @ W_in + b_in)
    for (int t = 0; t < NTYPES; t++) {
        sgemm512<1, 0><<<gg, 256>>>(x_all + (size_t)t * NNODES * FIN,
                                    W_in  + (size_t)t * FIN * HID,
                                    b_in  + (size_t)t * HID,
                                    h     + (size_t)t * NNODES * HID,
                                    NNODES, FIN);
    }

    // EDGE_TYPES = ((4,1),(1,0),(0,2),(2,3),(3,0),(1,4))
    const int ES[NET]   = {4, 1, 0, 2, 3, 1};
    const int ED[NET]   = {1, 0, 2, 3, 0, 4};
    const int EACC[NET] = {0, 0, 0, 0, 1, 0};  // first write per dst overwrites (no memset needed)

    for (int l = 0; l < 2; l++) {
        for (int t = 0; t < NET; t++) {
            const int s = ES[t], d = ED[t];
            // agg = h[d]  (GIN self term), then scatter-add neighbors
            cudaMemcpyAsync(agg, h + (size_t)d * NNODES * HID,
                            (size_t)NNODES * HID * sizeof(float),
                            cudaMemcpyDeviceToDevice);
            scatter_add_kernel<<<NEDGE, 128>>>(h + (size_t)s * NNODES * HID,
                                               edges + (size_t)t * 2 * NEDGE,
                                               edges + (size_t)t * 2 * NEDGE + NEDGE,
                                               agg);
            const size_t w = (size_t)l * NET + t;
            // mid = relu(agg @ W1 + b1)
            sgemm512<1, 0><<<gg, 256>>>(agg, W1 + w * HID * HID, b1 + w * HID,
                                        mid, NNODES, HID);
            // out[d] (+)= mid @ W2 + b2
            if (EACC[t])
                sgemm512<0, 1><<<gg, 256>>>(mid, W2 + w * HID * HID, b2 + w * HID,
                                            outb + (size_t)d * NNODES * HID, NNODES, HID);
            else
                sgemm512<0, 0><<<gg, 256>>>(mid, W2 + w * HID * HID, b2 + w * HID,
                                            outb + (size_t)d * NNODES * HID, NNODES, HID);
        }
        // h = relu(out) for all 5 types
        relu_kernel<<<1024, 256>>>(outb, h, NTYPES * NNODES * HID / 4);
    }

    // 2) output head on product nodes (type 0)
    head_kernel<<<(NNODES * 32 + 255) / 256, 256>>>(h, W_out, b_out, out, NNODES);
}

// round 3
// speedup vs baseline: 1.7204x; 1.7204x over previous
#include <cuda_runtime.h>
#include <cuda_bf16.h>
#include <cstdint>
#include <cstddef>

#define NNODES 20000
#define HID    512
#define NEDGE  160000
#define NTYPES 5
#define NET    6
#define FIN    64
#define NWMAT  12

// ---------------- scratch (__device__ globals; no allocs allowed) -------------
__device__ float g_h  [NTYPES * NNODES * HID];
__device__ float g_h2 [NTYPES * NNODES * HID];
__device__ float g_agg[NNODES * HID];
__device__ float g_tmp[NNODES * HID];
__device__ __nv_bfloat16 g_Ahi[NNODES * HID];
__device__ __nv_bfloat16 g_Alo[NNODES * HID];
__device__ __nv_bfloat16 g_Mhi[NNODES * HID];
__device__ __nv_bfloat16 g_Mlo[NNODES * HID];
__device__ __nv_bfloat16 g_W1hi[NWMAT * HID * HID];
__device__ __nv_bfloat16 g_W1lo[NWMAT * HID * HID];
__device__ __nv_bfloat16 g_W2hi[NWMAT * HID * HID];
__device__ __nv_bfloat16 g_W2lo[NWMAT * HID * HID];

// ---------------- family-common PTX helpers (sm_80+) --------------------------
__device__ __forceinline__ uint32_t smem_u32(const void* p) {
    uint32_t a;
    asm("{ .reg .u64 t; cvta.to.shared.u64 t, %1; cvt.u32.u64 %0, t; }" : "=r"(a) : "l"(p));
    return a;
}
__device__ __forceinline__ void cpasync16(uint32_t s, const void* g, int sz) {
    asm volatile("cp.async.cg.shared.global [%0], [%1], 16, %2;" :: "r"(s), "l"(g), "r"(sz));
}
__device__ __forceinline__ void cp_commit() { asm volatile("cp.async.commit_group;"); }
template<int N>
__device__ __forceinline__ void cp_wait() { asm volatile("cp.async.wait_group %0;" :: "n"(N)); }

__device__ __forceinline__ void ldsm4(uint32_t* r, uint32_t a) {
    asm volatile("ldmatrix.sync.aligned.m8n8.x4.shared.b16 {%0,%1,%2,%3}, [%4];"
                 : "=r"(r[0]), "=r"(r[1]), "=r"(r[2]), "=r"(r[3]) : "r"(a));
}
__device__ __forceinline__ void ldsm2(uint32_t* r, uint32_t a) {
    asm volatile("ldmatrix.sync.aligned.m8n8.x2.shared.b16 {%0,%1}, [%2];"
                 : "=r"(r[0]), "=r"(r[1]) : "r"(a));
}
__device__ __forceinline__ void mma16816(float* d, const uint32_t* a, const uint32_t* b) {
    asm volatile("mma.sync.aligned.m16n8k16.row.col.f32.bf16.bf16.f32 "
                 "{%0,%1,%2,%3}, {%4,%5,%6,%7}, {%8,%9}, {%0,%1,%2,%3};"
                 : "+f"(d[0]), "+f"(d[1]), "+f"(d[2]), "+f"(d[3])
                 : "r"(a[0]), "r"(a[1]), "r"(a[2]), "r"(a[3]), "r"(b[0]), "r"(b[1]));
}

// ---------------------------------------------------------------------
// Split-bf16 tensor GEMM on mma.sync (HMMA):
// C[M,512] = act(A @ W + bias), A = Ahi + Alo (bf16), W supplied transposed
// as B[n][k] hi/lo. CTA 128x128, BK=32, 8 warps (warp tile 64x32),
// products: Ahi*Bhi + Ahi*Blo + Alo*Bhi, fp32 accum.
// ---------------------------------------------------------------------
#define MS_A_HI 0
#define MS_A_LO 10240
#define MS_B_HI 20480
#define MS_B_LO 30720
#define MS_STAGE 40960
#define MS_TOTAL (2 * MS_STAGE)
#define NKT 16   // 512 / 32

template<int RELU, int ACCUM, int OUTSPLIT>
__global__ __launch_bounds__(256, 1)
void gemm_mma(const __nv_bfloat16* __restrict__ Ahi, const __nv_bfloat16* __restrict__ Alo,
              const __nv_bfloat16* __restrict__ Bhi, const __nv_bfloat16* __restrict__ Blo,
              const float* __restrict__ bias,
              float* __restrict__ C, const float* __restrict__ Cadd,
              __nv_bfloat16* __restrict__ Chi, __nv_bfloat16* __restrict__ Clo,
              int M)
{
    extern __shared__ char smem[];
    const uint32_t sb = smem_u32(smem);
    const int tid  = threadIdx.x;
    const int lane = tid & 31;
    const int wid  = tid >> 5;
    const int wm   = (wid >> 2) * 64;   // warp m-offset within CTA tile
    const int wn   = (wid & 3) * 32;    // warp n-offset
    const int bm   = blockIdx.x * 128;
    const int bn   = blockIdx.y * 128;

    auto load_stage = [&](int st, int kt) {
        const int kc = kt * 32;
        const uint32_t sbase = sb + st * MS_STAGE;
#pragma unroll
        for (int j = 0; j < 2; ++j) {
            const int c   = tid + j * 256;
            const int row = c >> 2;         // 0..127
            const int c16 = c & 3;          // 16B chunk within 64B row
            const uint32_t so = (uint32_t)(row * 80 + c16 * 16);
            const int gr = bm + row;
            const int sz = (gr < M) ? 16 : 0;
            const size_t ga = (size_t)gr * HID + kc + c16 * 8;
            cpasync16(sbase + MS_A_HI + so, Ahi + ga, sz);
            cpasync16(sbase + MS_A_LO + so, Alo + ga, sz);
            const size_t gb = (size_t)(bn + row) * HID + kc + c16 * 8;
            cpasync16(sbase + MS_B_HI + so, Bhi + gb, 16);
            cpasync16(sbase + MS_B_LO + so, Blo + gb, 16);
        }
        cp_commit();
    };

    float acc[4][4][4];
#pragma unroll
    for (int mi = 0; mi < 4; ++mi)
#pragma unroll
        for (int ni = 0; ni < 4; ++ni)
#pragma unroll
            for (int q = 0; q < 4; ++q) acc[mi][ni][q] = 0.f;

    load_stage(0, 0);

    // ldmatrix lane addressing (fixed per thread)
    const uint32_t a_row = (uint32_t)(lane & 15);
    const uint32_t a_k16 = (uint32_t)((lane >> 4) * 16);   // bytes
    const uint32_t b_row = (uint32_t)(lane & 7);
    const uint32_t b_k16 = (uint32_t)(((lane >> 3) & 1) * 16);

    for (int kt = 0; kt < NKT; ++kt) {
        if (kt + 1 < NKT) { load_stage((kt + 1) & 1, kt + 1); cp_wait<1>(); }
        else              { cp_wait<0>(); }
        __syncthreads();

        const uint32_t sbase = sb + (kt & 1) * MS_STAGE;
#pragma unroll
        for (int k2 = 0; k2 < 2; ++k2) {
            const uint32_t koff = (uint32_t)(k2 * 32);    // bytes within 64B row
            uint32_t ah[4][4], al[4][4], bh[4][2], bl[4][2];
#pragma unroll
            for (int mi = 0; mi < 4; ++mi) {
                uint32_t ad = sbase + (uint32_t)((wm + mi * 16 + a_row) * 80) + a_k16 + koff;
                ldsm4(ah[mi], ad + MS_A_HI);
                ldsm4(al[mi], ad + MS_A_LO);
            }
#pragma unroll
            for (int ni = 0; ni < 4; ++ni) {
                uint32_t bd = sbase + (uint32_t)((wn + ni * 8 + b_row) * 80) + b_k16 + koff;
                ldsm2(bh[ni], bd + MS_B_HI);
                ldsm2(bl[ni], bd + MS_B_LO);
            }
#pragma unroll
            for (int mi = 0; mi < 4; ++mi)
#pragma unroll
                for (int ni = 0; ni < 4; ++ni) {
                    mma16816(acc[mi][ni], ah[mi], bh[ni]);
                    mma16816(acc[mi][ni], ah[mi], bl[ni]);
                    mma16816(acc[mi][ni], al[mi], bh[ni]);
                }
        }
        __syncthreads();
    }

    // ---- epilogue ----
#pragma unroll
    for (int mi = 0; mi < 4; ++mi) {
        const int r0 = bm + wm + mi * 16 + (lane >> 2);
#pragma unroll
        for (int half = 0; half < 2; ++half) {
            const int r = r0 + half * 8;
            if (r >= M) continue;
#pragma unroll
            for (int ni = 0; ni < 4; ++ni) {
                const int c = bn + wn + ni * 8 + (lane & 3) * 2;
                float v0 = acc[mi][ni][half * 2 + 0] + bias[c];
                float v1 = acc[mi][ni][half * 2 + 1] + bias[c + 1];
                if (ACCUM) {
                    const float2 o = *(const float2*)(Cadd + (size_t)r * HID + c);
                    v0 += o.x; v1 += o.y;
                }
                if (RELU) { v0 = fmaxf(v0, 0.f); v1 = fmaxf(v1, 0.f); }
                if (OUTSPLIT) {
                    __nv_bfloat16 h0 = __float2bfloat16(v0), h1 = __float2bfloat16(v1);
                    float l0 = v0 - __bfloat162float(h0);
                    float l1 = v1 - __bfloat162float(h1);
                    __nv_bfloat16 q0 = __float2bfloat16(l0), q1 = __float2bfloat16(l1);
                    uint32_t hp = ((uint32_t)__bfloat16_as_ushort(h1) << 16) | __bfloat16_as_ushort(h0);
                    uint32_t lp = ((uint32_t)__bfloat16_as_ushort(q1) << 16) | __bfloat16_as_ushort(q0);
                    *(uint32_t*)(Chi + (size_t)r * HID + c) = hp;
                    *(uint32_t*)(Clo + (size_t)r * HID + c) = lp;
                } else {
                    *(float2*)(C + (size_t)r * HID + c) = make_float2(v0, v1);
                }
            }
        }
    }
}

// ---------------------------------------------------------------------
// SIMT SGEMM for the K=64 input projection
// ---------------------------------------------------------------------
__global__ __launch_bounds__(256, 2)
void sgemm512(const float* __restrict__ A, const float* __restrict__ W,
              const float* __restrict__ bias, float* __restrict__ C,
              int M, int K)
{
    __shared__ float As[8][132];
    __shared__ float Bs[8][128];
    const int bm = blockIdx.x * 128, bn = blockIdx.y * 128;
    const int tid = threadIdx.x;
    const int tx = tid & 15, ty = tid >> 4;
    const int a_row = tid >> 1, a_col = (tid & 1) * 4;
    const int b_row = tid >> 5, b_col = (tid & 31) * 4;

    float acc[8][8];
#pragma unroll
    for (int i = 0; i < 8; i++)
#pragma unroll
        for (int j = 0; j < 8; j++) acc[i][j] = 0.f;

    const int gr = bm + a_row;
    const float* Aptr = A + (size_t)gr * K + a_col;
    const float* Wptr = W + (size_t)b_row * HID + bn + b_col;

    for (int k0 = 0; k0 < K; k0 += 8) {
        float4 av = make_float4(0.f, 0.f, 0.f, 0.f);
        if (gr < M) av = *(const float4*)(Aptr + k0);
        As[a_col + 0][a_row] = av.x;
        As[a_col + 1][a_row] = av.y;
        As[a_col + 2][a_row] = av.z;
        As[a_col + 3][a_row] = av.w;
        *(float4*)&Bs[b_row][b_col] = *(const float4*)(Wptr + (size_t)k0 * HID);
        __syncthreads();
#pragma unroll
        for (int k = 0; k < 8; k++) {
            float a[8], b[8];
            *(float4*)&a[0] = *(const float4*)&As[k][ty * 4];
            *(float4*)&a[4] = *(const float4*)&As[k][64 + ty * 4];
            *(float4*)&b[0] = *(const float4*)&Bs[k][tx * 4];
            *(float4*)&b[4] = *(const float4*)&Bs[k][64 + tx * 4];
#pragma unroll
            for (int i = 0; i < 8; i++)
#pragma unroll
                for (int j = 0; j < 8; j++)
                    acc[i][j] = fmaf(a[i], b[j], acc[i][j]);
        }
        __syncthreads();
    }
#pragma unroll
    for (int ii = 0; ii < 2; ii++) {
#pragma unroll
        for (int i2 = 0; i2 < 4; i2++) {
            int r = bm + ii * 64 + ty * 4 + i2;
            if (r >= M) continue;
#pragma unroll
            for (int jj = 0; jj < 2; jj++) {
                int c = bn + jj * 64 + tx * 4;
                float4 bb = *(const float4*)(bias + c);
                float4 v;
                v.x = fmaxf(acc[ii*4+i2][jj*4+0] + bb.x, 0.f);
                v.y = fmaxf(acc[ii*4+i2][jj*4+1] + bb.y, 0.f);
                v.z = fmaxf(acc[ii*4+i2][jj*4+2] + bb.z, 0.f);
                v.w = fmaxf(acc[ii*4+i2][jj*4+3] + bb.w, 0.f);
                *(float4*)(C + (size_t)r * HID + c) = v;
            }
        }
    }
}

// ---------------------------------------------------------------------
__global__ void scatter_add_kernel(const float* __restrict__ hsrc,
                                   const int* __restrict__ srcI,
                                   const int* __restrict__ dstI,
                                   float* __restrict__ agg)
{
    const int e = blockIdx.x;
    const int s = srcI[e];
    const int d = dstI[e];
    const int t4 = threadIdx.x * 4;
    float4 v = *(const float4*)(hsrc + (size_t)s * HID + t4);
    float* p = agg + (size_t)d * HID + t4;
    asm volatile("red.global.add.v4.f32 [%0], {%1, %2, %3, %4};"
                 :: "l"(p), "f"(v.x), "f"(v.y), "f"(v.z), "f"(v.w) : "memory");
}

// agg (scatter result) + h_dst  -> bf16 hi/lo split
__global__ void split_add_kernel(const float* __restrict__ a, const float* __restrict__ b,
                                 __nv_bfloat16* __restrict__ hi, __nv_bfloat16* __restrict__ lo,
                                 int n4)
{
    int i = blockIdx.x * blockDim.x + threadIdx.x;
    if (i >= n4) return;
    float4 va = ((const float4*)a)[i];
    float4 vb = ((const float4*)b)[i];
    float x0 = va.x + vb.x, x1 = va.y + vb.y, x2 = va.z + vb.z, x3 = va.w + vb.w;
    __nv_bfloat16 h0 = __float2bfloat16(x0), h1 = __float2bfloat16(x1);
    __nv_bfloat16 h2 = __float2bfloat16(x2), h3 = __float2bfloat16(x3);
    __nv_bfloat16 l0 = __float2bfloat16(x0 - __bfloat162float(h0));
    __nv_bfloat16 l1 = __float2bfloat16(x1 - __bfloat162float(h1));
    __nv_bfloat16 l2 = __float2bfloat16(x2 - __bfloat162float(h2));
    __nv_bfloat16 l3 = __float2bfloat16(x3 - __bfloat162float(h3));
    uint2 hv, lv;
    hv.x = ((uint32_t)__bfloat16_as_ushort(h1) << 16) | __bfloat16_as_ushort(h0);
    hv.y = ((uint32_t)__bfloat16_as_ushort(h3) << 16) | __bfloat16_as_ushort(h2);
    lv.x = ((uint32_t)__bfloat16_as_ushort(l1) << 16) | __bfloat16_as_ushort(l0);
    lv.y = ((uint32_t)__bfloat16_as_ushort(l3) << 16) | __bfloat16_as_ushort(l2);
    ((uint2*)hi)[i] = hv;
    ((uint2*)lo)[i] = lv;
}

// transpose + split weights: W[m][k][n] fp32  ->  Wt_hi/lo[m][n][k] bf16
__global__ void wconv_kernel(const float* __restrict__ W,
                             __nv_bfloat16* __restrict__ Whi, __nv_bfloat16* __restrict__ Wlo)
{
    __shared__ float t[32][33];
    const int m = blockIdx.z;
    const int k0 = blockIdx.x * 32, n0 = blockIdx.y * 32;
    const int tx = threadIdx.x, ty = threadIdx.y;
    const float* Wm = W + (size_t)m * HID * HID;
#pragma unroll
    for (int i = 0; i < 4; i++)
        t[ty + i * 8][tx] = Wm[(size_t)(k0 + ty + i * 8) * HID + n0 + tx];
    __syncthreads();
    const size_t ob = (size_t)m * HID * HID;
#pragma unroll
    for (int i = 0; i < 4; i++) {
        int n = n0 + ty + i * 8, k = k0 + tx;
        float v = t[tx][ty + i * 8];
        __nv_bfloat16 h = __float2bfloat16(v);
        Whi[ob + (size_t)n * HID + k] = h;
        Wlo[ob + (size_t)n * HID + k] = __float2bfloat16(v - __bfloat162float(h));
    }
}

// ---------------------------------------------------------------------
__global__ void head_kernel(const float* __restrict__ h0, const float* __restrict__ Wout,
                            const float* __restrict__ bout, float* __restrict__ out, int M)
{
    const int gw = (int)((blockIdx.x * (size_t)blockDim.x + threadIdx.x) >> 5);
    const int lane = threadIdx.x & 31;
    if (gw >= M) return;
    const float* row = h0 + (size_t)gw * HID;
    float s = 0.f;
#pragma unroll
    for (int i = 0; i < 4; i++) {
        int c = (lane + i * 32) * 4;
        float4 a = *(const float4*)(row + c);
        float4 w = *(const float4*)(Wout + c);
        s += a.x * w.x + a.y * w.y + a.z * w.z + a.w * w.w;
    }
#pragma unroll
    for (int o = 16; o; o >>= 1) s += __shfl_xor_sync(0xffffffffu, s, o);
    if (lane == 0) out[gw] = s + bout[0];
}

// ---------------------------------------------------------------------
extern "C" void kernel_launch(void* const* d_in, const int* in_sizes, int n_in,
                              void* d_out, int out_size)
{
    const float* x_all = (const float*)d_in[0];
    const float* W_in  = (const float*)d_in[1];
    const float* b_in  = (const float*)d_in[2];
    const float* W1    = (const float*)d_in[3];
    const float* b1    = (const float*)d_in[4];
    const float* W2    = (const float*)d_in[5];
    const float* b2    = (const float*)d_in[6];
    const float* W_out = (const float*)d_in[7];
    const float* b_out = (const float*)d_in[8];
    const int*   edges = (const int*)d_in[9];
    float* out = (float*)d_out;

    float *h, *h2, *agg, *tmp;
    __nv_bfloat16 *Ahi, *Alo, *Mhi, *Mlo, *W1hi, *W1lo, *W2hi, *W2lo;
    cudaGetSymbolAddress((void**)&h,   g_h);
    cudaGetSymbolAddress((void**)&h2,  g_h2);
    cudaGetSymbolAddress((void**)&agg, g_agg);
    cudaGetSymbolAddress((void**)&tmp, g_tmp);
    cudaGetSymbolAddress((void**)&Ahi, g_Ahi);
    cudaGetSymbolAddress((void**)&Alo, g_Alo);
    cudaGetSymbolAddress((void**)&Mhi, g_Mhi);
    cudaGetSymbolAddress((void**)&Mlo, g_Mlo);
    cudaGetSymbolAddress((void**)&W1hi, g_W1hi);
    cudaGetSymbolAddress((void**)&W1lo, g_W1lo);
    cudaGetSymbolAddress((void**)&W2hi, g_W2hi);
    cudaGetSymbolAddress((void**)&W2lo, g_W2lo);

    cudaFuncSetAttribute(gemm_mma<1,0,1>, cudaFuncAttributeMaxDynamicSharedMemorySize, MS_TOTAL);
    cudaFuncSetAttribute(gemm_mma<0,0,0>, cudaFuncAttributeMaxDynamicSharedMemorySize, MS_TOTAL);
    cudaFuncSetAttribute(gemm_mma<1,0,0>, cudaFuncAttributeMaxDynamicSharedMemorySize, MS_TOTAL);
    cudaFuncSetAttribute(gemm_mma<1,1,0>, cudaFuncAttributeMaxDynamicSharedMemorySize, MS_TOTAL);

    const size_t TYPE_OFF = (size_t)NNODES * HID;
    const size_t WOFF = (size_t)HID * HID;
    const dim3 ggs((NNODES + 127) / 128, 4);     // SIMT input proj grid
    const dim3 ggt((NNODES + 127) / 128, 4);     // mma gemm grid (BN=128)
    const int n4 = NNODES * HID / 4;

    // 0) weight transpose + bf16 split
    wconv_kernel<<<dim3(16, 16, NWMAT), dim3(32, 8)>>>(W1, W1hi, W1lo);
    wconv_kernel<<<dim3(16, 16, NWMAT), dim3(32, 8)>>>(W2, W2hi, W2lo);

    // 1) input projection per node type: h = relu(x @ W_in + b_in)
    for (int t = 0; t < NTYPES; t++) {
        sgemm512<<<ggs, 256>>>(x_all + (size_t)t * NNODES * FIN,
                               W_in + (size_t)t * FIN * HID,
                               b_in + (size_t)t * HID,
                               h + (size_t)t * TYPE_OFF, NNODES, FIN);
    }

    // EDGE_TYPES = ((4,1),(1,0),(0,2),(2,3),(3,0),(1,4))
    const int ES[NET] = {4, 1, 0, 2, 3, 1};
    const int ED[NET] = {1, 0, 2, 3, 0, 4};

    float* cur = h;
    float* nxt = h2;
    for (int l = 0; l < 2; l++) {
        for (int t = 0; t < NET; t++) {
            const int s = ES[t], d = ED[t];
            const size_t w = (size_t)l * NET + t;
            cudaMemsetAsync(agg, 0, TYPE_OFF * sizeof(float));
            scatter_add_kernel<<<NEDGE, 128>>>(cur + (size_t)s * TYPE_OFF,
                                               edges + (size_t)t * 2 * NEDGE,
                                               edges + (size_t)t * 2 * NEDGE + NEDGE,
                                               agg);
            // A = agg + h[d]  -> bf16 hi/lo
            split_add_kernel<<<(n4 + 255) / 256, 256>>>(agg, cur + (size_t)d * TYPE_OFF,
                                                        Ahi, Alo, n4);
            // mid = relu(A @ W1 + b1) -> bf16 hi/lo directly
            gemm_mma<1,0,1><<<ggt, 256, MS_TOTAL>>>(Ahi, Alo, W1hi + w * WOFF, W1lo + w * WOFF,
                                                    b1 + w * HID, nullptr, nullptr, Mhi, Mlo, NNODES);
            // y = mid @ W2 + b2 ; HeteroConv sum + relu fused into last writer per dst
            if (t == 1) {          // dst 0, partial (t=4 also hits dst 0)
                gemm_mma<0,0,0><<<ggt, 256, MS_TOTAL>>>(Mhi, Mlo, W2hi + w * WOFF, W2lo + w * WOFF,
                                                        b2 + w * HID, tmp, nullptr, nullptr, nullptr, NNODES);
            } else if (t == 4) {   // dst 0, final: add tmp, relu
                gemm_mma<1,1,0><<<ggt, 256, MS_TOTAL>>>(Mhi, Mlo, W2hi + w * WOFF, W2lo + w * WOFF,
                                                        b2 + w * HID, nxt + 0 * TYPE_OFF, tmp,
                                                        nullptr, nullptr, NNODES);
            } else {               // single writer: relu directly
                gemm_mma<1,0,0><<<ggt, 256, MS_TOTAL>>>(Mhi, Mlo, W2hi + w * WOFF, W2lo + w * WOFF,
                                                        b2 + w * HID, nxt + (size_t)d * TYPE_OFF, nullptr,
                                                        nullptr, nullptr, NNODES);
            }
        }
        float* sw = cur; cur = nxt; nxt = sw;
    }

    // 2) output head on 'product' nodes (type 0)
    head_kernel<<<(NNODES * 32 + 255) / 256, 256>>>(cur, W_out, b_out, out, NNODES);
}

// round 4
// speedup vs baseline: 1.8448x; 1.0723x over previous
#include <cuda_runtime.h>
#include <cuda_bf16.h>
#include <cstdint>
#include <cstddef>

#define NNODES 20000
#define HID    512
#define NEDGE  160000
#define NTYPES 5
#define NET    6
#define FIN    64
#define NWMAT  12

// ---------------- scratch (__device__ globals; no allocs allowed) -------------
__device__ float g_h  [NTYPES * NNODES * HID];
__device__ float g_h2 [NTYPES * NNODES * HID];
__device__ float g_agg[NET][NNODES * HID];
__device__ float g_tmp[NNODES * HID];
__device__ __nv_bfloat16 g_Ahi[NET][NNODES * HID];
__device__ __nv_bfloat16 g_Alo[NET][NNODES * HID];
__device__ __nv_bfloat16 g_Mhi[NNODES * HID];
__device__ __nv_bfloat16 g_Mlo[NNODES * HID];
__device__ __nv_bfloat16 g_xhi[NTYPES * NNODES * FIN];
__device__ __nv_bfloat16 g_xlo[NTYPES * NNODES * FIN];
__device__ __nv_bfloat16 g_Winhi[NTYPES * HID * FIN];
__device__ __nv_bfloat16 g_Winlo[NTYPES * HID * FIN];
__device__ __nv_bfloat16 g_W1hi[NWMAT * HID * HID];
__device__ __nv_bfloat16 g_W1lo[NWMAT * HID * HID];
__device__ __nv_bfloat16 g_W2hi[NWMAT * HID * HID];
__device__ __nv_bfloat16 g_W2lo[NWMAT * HID * HID];

// ---------------- family-common PTX helpers (sm_80+) --------------------------
__device__ __forceinline__ uint32_t smem_u32(const void* p) {
    uint32_t a;
    asm("{ .reg .u64 t; cvta.to.shared.u64 t, %1; cvt.u32.u64 %0, t; }" : "=r"(a) : "l"(p));
    return a;
}
__device__ __forceinline__ void cpasync16(uint32_t s, const void* g, int sz) {
    asm volatile("cp.async.cg.shared.global [%0], [%1], 16, %2;" :: "r"(s), "l"(g), "r"(sz));
}
__device__ __forceinline__ void cp_commit() { asm volatile("cp.async.commit_group;"); }
template<int N>
__device__ __forceinline__ void cp_wait() { asm volatile("cp.async.wait_group %0;" :: "n"(N)); }

__device__ __forceinline__ void ldsm4(uint32_t* r, uint32_t a) {
    asm volatile("ldmatrix.sync.aligned.m8n8.x4.shared.b16 {%0,%1,%2,%3}, [%4];"
                 : "=r"(r[0]), "=r"(r[1]), "=r"(r[2]), "=r"(r[3]) : "r"(a));
}
__device__ __forceinline__ void ldsm2(uint32_t* r, uint32_t a) {
    asm volatile("ldmatrix.sync.aligned.m8n8.x2.shared.b16 {%0,%1}, [%2];"
                 : "=r"(r[0]), "=r"(r[1]) : "r"(a));
}
__device__ __forceinline__ void mma16816(float* d, const uint32_t* a, const uint32_t* b) {
    asm volatile("mma.sync.aligned.m16n8k16.row.col.f32.bf16.bf16.f32 "
                 "{%0,%1,%2,%3}, {%4,%5,%6,%7}, {%8,%9}, {%0,%1,%2,%3};"
                 : "+f"(d[0]), "+f"(d[1]), "+f"(d[2]), "+f"(d[3])
                 : "r"(a[0]), "r"(a[1]), "r"(a[2]), "r"(a[3]), "r"(b[0]), "r"(b[1]));
}

// ---------------------------------------------------------------------
// Split-bf16 tensor GEMM on mma.sync (HMMA), 3-stage cp.async pipeline.
// C[M,512] = act(A @ W + bias); A = Ahi + Alo (bf16, row length LDK);
// W supplied transposed as B[n][k] hi/lo (row length LDK).
// CTA 128x128, BK=32, 8 warps (warp tile 64x32),
// products: Ahi*Bhi + Ahi*Blo + Alo*Bhi, fp32 accum.
// ---------------------------------------------------------------------
#define MS_A_HI 0
#define MS_A_LO 10240
#define MS_B_HI 20480
#define MS_B_LO 30720
#define MS_STAGE 40960
#define MS_TOTAL (3 * MS_STAGE)

template<int RELU, int ACCUM, int OUTSPLIT, int LDK>
__global__ __launch_bounds__(256, 1)
void gemm_mma(const __nv_bfloat16* __restrict__ Ahi, const __nv_bfloat16* __restrict__ Alo,
              const __nv_bfloat16* __restrict__ Bhi, const __nv_bfloat16* __restrict__ Blo,
              const float* __restrict__ bias,
              float* __restrict__ C, const float* __restrict__ Cadd,
              __nv_bfloat16* __restrict__ Chi, __nv_bfloat16* __restrict__ Clo,
              int M)
{
    constexpr int NKT = LDK / 32;
    extern __shared__ char smem[];
    const uint32_t sb = smem_u32(smem);
    const int tid  = threadIdx.x;
    const int lane = tid & 31;
    const int wid  = tid >> 5;
    const int wm   = (wid >> 2) * 64;
    const int wn   = (wid & 3) * 32;
    const int bm   = blockIdx.x * 128;
    const int bn   = blockIdx.y * 128;

    auto load_stage = [&](int st, int kt) {
        const int kc = kt * 32;
        const uint32_t sbase = sb + st * MS_STAGE;
#pragma unroll
        for (int j = 0; j < 2; ++j) {
            const int c   = tid + j * 256;
            const int row = c >> 2;
            const int c16 = c & 3;
            const uint32_t so = (uint32_t)(row * 80 + c16 * 16);
            const int gr = bm + row;
            const int sz = (gr < M) ? 16 : 0;
            const size_t ga = (size_t)gr * LDK + kc + c16 * 8;
            cpasync16(sbase + MS_A_HI + so, Ahi + ga, sz);
            cpasync16(sbase + MS_A_LO + so, Alo + ga, sz);
            const size_t gb = (size_t)(bn + row) * LDK + kc + c16 * 8;
            cpasync16(sbase + MS_B_HI + so, Bhi + gb, 16);
            cpasync16(sbase + MS_B_LO + so, Blo + gb, 16);
        }
        cp_commit();
    };

    float acc[4][4][4];
#pragma unroll
    for (int mi = 0; mi < 4; ++mi)
#pragma unroll
        for (int ni = 0; ni < 4; ++ni)
#pragma unroll
            for (int q = 0; q < 4; ++q) acc[mi][ni][q] = 0.f;

    load_stage(0, 0);
    if (NKT > 1) load_stage(1, 1);

    const uint32_t a_row = (uint32_t)(lane & 15);
    const uint32_t a_k16 = (uint32_t)((lane >> 4) * 16);
    const uint32_t b_row = (uint32_t)(lane & 7);
    const uint32_t b_k16 = (uint32_t)(((lane >> 3) & 1) * 16);

#pragma unroll 1
    for (int kt = 0; kt < NKT; ++kt) {
        if (kt >= NKT - 1) cp_wait<0>();
        else               cp_wait<1>();
        __syncthreads();
        if (kt + 2 < NKT) load_stage((kt + 2) % 3, kt + 2);

        const uint32_t sbase = sb + (uint32_t)(kt % 3) * MS_STAGE;
#pragma unroll
        for (int k2 = 0; k2 < 2; ++k2) {
            const uint32_t koff = (uint32_t)(k2 * 32);
            uint32_t ah[4][4], al[4][4], bh[4][2], bl[4][2];
#pragma unroll
            for (int mi = 0; mi < 4; ++mi) {
                uint32_t ad = sbase + (uint32_t)((wm + mi * 16 + a_row) * 80) + a_k16 + koff;
                ldsm4(ah[mi], ad + MS_A_HI);
                ldsm4(al[mi], ad + MS_A_LO);
            }
#pragma unroll
            for (int ni = 0; ni < 4; ++ni) {
                uint32_t bd = sbase + (uint32_t)((wn + ni * 8 + b_row) * 80) + b_k16 + koff;
                ldsm2(bh[ni], bd + MS_B_HI);
                ldsm2(bl[ni], bd + MS_B_LO);
            }
#pragma unroll
            for (int mi = 0; mi < 4; ++mi)
#pragma unroll
                for (int ni = 0; ni < 4; ++ni) {
                    mma16816(acc[mi][ni], ah[mi], bh[ni]);
                    mma16816(acc[mi][ni], ah[mi], bl[ni]);
                    mma16816(acc[mi][ni], al[mi], bh[ni]);
                }
        }
    }

    // ---- epilogue ----
#pragma unroll
    for (int mi = 0; mi < 4; ++mi) {
        const int r0 = bm + wm + mi * 16 + (lane >> 2);
#pragma unroll
        for (int half = 0; half < 2; ++half) {
            const int r = r0 + half * 8;
            if (r >= M) continue;
#pragma unroll
            for (int ni = 0; ni < 4; ++ni) {
                const int c = bn + wn + ni * 8 + (lane & 3) * 2;
                float v0 = acc[mi][ni][half * 2 + 0] + bias[c];
                float v1 = acc[mi][ni][half * 2 + 1] + bias[c + 1];
                if (ACCUM) {
                    const float2 o = *(const float2*)(Cadd + (size_t)r * HID + c);
                    v0 += o.x; v1 += o.y;
                }
                if (RELU) { v0 = fmaxf(v0, 0.f); v1 = fmaxf(v1, 0.f); }
                if (OUTSPLIT) {
                    __nv_bfloat16 h0 = __float2bfloat16(v0), h1 = __float2bfloat16(v1);
                    float l0 = v0 - __bfloat162float(h0);
                    float l1 = v1 - __bfloat162float(h1);
                    __nv_bfloat16 q0 = __float2bfloat16(l0), q1 = __float2bfloat16(l1);
                    uint32_t hp = ((uint32_t)__bfloat16_as_ushort(h1) << 16) | __bfloat16_as_ushort(h0);
                    uint32_t lp = ((uint32_t)__bfloat16_as_ushort(q1) << 16) | __bfloat16_as_ushort(q0);
                    *(uint32_t*)(Chi + (size_t)r * HID + c) = hp;
                    *(uint32_t*)(Clo + (size_t)r * HID + c) = lp;
                } else {
                    *(float2*)(C + (size_t)r * HID + c) = make_float2(v0, v1);
                }
            }
        }
    }
}

// ---------------------------------------------------------------------
__global__ void scatter_add_kernel(const float* __restrict__ hsrc,
                                   const int* __restrict__ srcI,
                                   const int* __restrict__ dstI,
                                   float* __restrict__ agg)
{
    const int e = blockIdx.x;
    const int s = srcI[e];
    const int d = dstI[e];
    const int t4 = threadIdx.x * 4;
    float4 v = *(const float4*)(hsrc + (size_t)s * HID + t4);
    float* p = agg + (size_t)d * HID + t4;
    asm volatile("red.global.add.v4.f32 [%0], {%1, %2, %3, %4};"
                 :: "l"(p), "f"(v.x), "f"(v.y), "f"(v.z), "f"(v.w) : "memory");
}

// a + b -> bf16 hi/lo split
__global__ void split_add_kernel(const float* __restrict__ a, const float* __restrict__ b,
                                 __nv_bfloat16* __restrict__ hi, __nv_bfloat16* __restrict__ lo,
                                 int n4)
{
    int i = blockIdx.x * blockDim.x + threadIdx.x;
    if (i >= n4) return;
    float4 va = ((const float4*)a)[i];
    float4 vb = ((const float4*)b)[i];
    float x0 = va.x + vb.x, x1 = va.y + vb.y, x2 = va.z + vb.z, x3 = va.w + vb.w;
    __nv_bfloat16 h0 = __float2bfloat16(x0), h1 = __float2bfloat16(x1);
    __nv_bfloat16 h2 = __float2bfloat16(x2), h3 = __float2bfloat16(x3);
    __nv_bfloat16 l0 = __float2bfloat16(x0 - __bfloat162float(h0));
    __nv_bfloat16 l1 = __float2bfloat16(x1 - __bfloat162float(h1));
    __nv_bfloat16 l2 = __float2bfloat16(x2 - __bfloat162float(h2));
    __nv_bfloat16 l3 = __float2bfloat16(x3 - __bfloat162float(h3));
    uint2 hv, lv;
    hv.x = ((uint32_t)__bfloat16_as_ushort(h1) << 16) | __bfloat16_as_ushort(h0);
    hv.y = ((uint32_t)__bfloat16_as_ushort(h3) << 16) | __bfloat16_as_ushort(h2);
    lv.x = ((uint32_t)__bfloat16_as_ushort(l1) << 16) | __bfloat16_as_ushort(l0);
    lv.y = ((uint32_t)__bfloat16_as_ushort(l3) << 16) | __bfloat16_as_ushort(l2);
    ((uint2*)hi)[i] = hv;
    ((uint2*)lo)[i] = lv;
}

// x -> bf16 hi/lo split (no add)
__global__ void split_kernel(const float* __restrict__ a,
                             __nv_bfloat16* __restrict__ hi, __nv_bfloat16* __restrict__ lo,
                             int n4)
{
    int i = blockIdx.x * blockDim.x + threadIdx.x;
    if (i >= n4) return;
    float4 va = ((const float4*)a)[i];
    __nv_bfloat16 h0 = __float2bfloat16(va.x), h1 = __float2bfloat16(va.y);
    __nv_bfloat16 h2 = __float2bfloat16(va.z), h3 = __float2bfloat16(va.w);
    __nv_bfloat16 l0 = __float2bfloat16(va.x - __bfloat162float(h0));
    __nv_bfloat16 l1 = __float2bfloat16(va.y - __bfloat162float(h1));
    __nv_bfloat16 l2 = __float2bfloat16(va.z - __bfloat162float(h2));
    __nv_bfloat16 l3 = __float2bfloat16(va.w - __bfloat162float(h3));
    uint2 hv, lv;
    hv.x = ((uint32_t)__bfloat16_as_ushort(h1) << 16) | __bfloat16_as_ushort(h0);
    hv.y = ((uint32_t)__bfloat16_as_ushort(h3) << 16) | __bfloat16_as_ushort(h2);
    lv.x = ((uint32_t)__bfloat16_as_ushort(l1) << 16) | __bfloat16_as_ushort(l0);
    lv.y = ((uint32_t)__bfloat16_as_ushort(l3) << 16) | __bfloat16_as_ushort(l2);
    ((uint2*)hi)[i] = hv;
    ((uint2*)lo)[i] = lv;
}

// transpose + split weights: W[m][Kd][Nd] fp32 -> Wt_hi/lo[m][Nd][Kd] bf16
__global__ void wconv_kernel(const float* __restrict__ W,
                             __nv_bfloat16* __restrict__ Whi, __nv_bfloat16* __restrict__ Wlo,
                             int Kd, int Nd)
{
    __shared__ float t[32][33];
    const int m = blockIdx.z;
    const int k0 = blockIdx.x * 32, n0 = blockIdx.y * 32;
    const int tx = threadIdx.x, ty = threadIdx.y;
    const float* Wm = W + (size_t)m * Kd * Nd;
#pragma unroll
    for (int i = 0; i < 4; i++)
        t[ty + i * 8][tx] = Wm[(size_t)(k0 + ty + i * 8) * Nd + n0 + tx];
    __syncthreads();
    const size_t ob = (size_t)m * Kd * Nd;
#pragma unroll
    for (int i = 0; i < 4; i++) {
        int n = n0 + ty + i * 8, k = k0 + tx;
        float v = t[tx][ty + i * 8];
        __nv_bfloat16 h = __float2bfloat16(v);
        Whi[ob + (size_t)n * Kd + k] = h;
        Wlo[ob + (size_t)n * Kd + k] = __float2bfloat16(v - __bfloat162float(h));
    }
}

// ---------------------------------------------------------------------
__global__ void head_kernel(const float* __restrict__ h0, const float* __restrict__ Wout,
                            const float* __restrict__ bout, float* __restrict__ out, int M)
{
    const int gw = (int)((blockIdx.x * (size_t)blockDim.x + threadIdx.x) >> 5);
    const int lane = threadIdx.x & 31;
    if (gw >= M) return;
    const float* row = h0 + (size_t)gw * HID;
    float s = 0.f;
#pragma unroll
    for (int i = 0; i < 4; i++) {
        int c = (lane + i * 32) * 4;
        float4 a = *(const float4*)(row + c);
        float4 w = *(const float4*)(Wout + c);
        s += a.x * w.x + a.y * w.y + a.z * w.z + a.w * w.w;
    }
#pragma unroll
    for (int o = 16; o; o >>= 1) s += __shfl_xor_sync(0xffffffffu, s, o);
    if (lane == 0) out[gw] = s + bout[0];
}

// ---------------------------------------------------------------------
extern "C" void kernel_launch(void* const* d_in, const int* in_sizes, int n_in,
                              void* d_out, int out_size)
{
    const float* x_all = (const float*)d_in[0];
    const float* W_in  = (const float*)d_in[1];
    const float* b_in  = (const float*)d_in[2];
    const float* W1    = (const float*)d_in[3];
    const float* b1    = (const float*)d_in[4];
    const float* W2    = (const float*)d_in[5];
    const float* b2    = (const float*)d_in[6];
    const float* W_out = (const float*)d_in[7];
    const float* b_out = (const float*)d_in[8];
    const int*   edges = (const int*)d_in[9];
    float* out = (float*)d_out;

    float *h, *h2, *agg, *tmp;
    __nv_bfloat16 *Ahi, *Alo, *Mhi, *Mlo, *xhi, *xlo, *Winhi, *Winlo, *W1hi, *W1lo, *W2hi, *W2lo;
    cudaGetSymbolAddress((void**)&h,    g_h);
    cudaGetSymbolAddress((void**)&h2,   g_h2);
    cudaGetSymbolAddress((void**)&agg,  g_agg);
    cudaGetSymbolAddress((void**)&tmp,  g_tmp);
    cudaGetSymbolAddress((void**)&Ahi,  g_Ahi);
    cudaGetSymbolAddress((void**)&Alo,  g_Alo);
    cudaGetSymbolAddress((void**)&Mhi,  g_Mhi);
    cudaGetSymbolAddress((void**)&Mlo,  g_Mlo);
    cudaGetSymbolAddress((void**)&xhi,  g_xhi);
    cudaGetSymbolAddress((void**)&xlo,  g_xlo);
    cudaGetSymbolAddress((void**)&Winhi, g_Winhi);
    cudaGetSymbolAddress((void**)&Winlo, g_Winlo);
    cudaGetSymbolAddress((void**)&W1hi, g_W1hi);
    cudaGetSymbolAddress((void**)&W1lo, g_W1lo);
    cudaGetSymbolAddress((void**)&W2hi, g_W2hi);
    cudaGetSymbolAddress((void**)&W2lo, g_W2lo);

    cudaFuncSetAttribute(gemm_mma<1,0,1,512>, cudaFuncAttributeMaxDynamicSharedMemorySize, MS_TOTAL);
    cudaFuncSetAttribute(gemm_mma<0,0,0,512>, cudaFuncAttributeMaxDynamicSharedMemorySize, MS_TOTAL);
    cudaFuncSetAttribute(gemm_mma<1,0,0,512>, cudaFuncAttributeMaxDynamicSharedMemorySize, MS_TOTAL);
    cudaFuncSetAttribute(gemm_mma<1,1,0,512>, cudaFuncAttributeMaxDynamicSharedMemorySize, MS_TOTAL);
    cudaFuncSetAttribute(gemm_mma<1,0,0,64>,  cudaFuncAttributeMaxDynamicSharedMemorySize, MS_TOTAL);

    const size_t TYPE_OFF = (size_t)NNODES * HID;
    const size_t WOFF = (size_t)HID * HID;
    const dim3 ggt((NNODES + 127) / 128, 4);
    const int n4 = NNODES * HID / 4;

    // ---- side stream + events (fresh per call; fork-join capture pattern) ----
    cudaStream_t s1;
    cudaStreamCreateWithFlags(&s1, cudaStreamNonBlocking);
    cudaEvent_t evLayer[2], evP[2][NET];
    for (int l = 0; l < 2; l++) {
        cudaEventCreateWithFlags(&evLayer[l], cudaEventDisableTiming);
        for (int t = 0; t < NET; t++)
            cudaEventCreateWithFlags(&evP[l][t], cudaEventDisableTiming);
    }

    // EDGE_TYPES = ((4,1),(1,0),(0,2),(2,3),(3,0),(1,4))
    const int ES[NET] = {4, 1, 0, 2, 3, 1};
    const int ED[NET] = {1, 0, 2, 3, 0, 4};

    // ---- stream0: weight prep + input projection ----
    wconv_kernel<<<dim3(16, 16, NWMAT), dim3(32, 8)>>>(W1, W1hi, W1lo, HID, HID);
    wconv_kernel<<<dim3(16, 16, NWMAT), dim3(32, 8)>>>(W2, W2hi, W2lo, HID, HID);
    wconv_kernel<<<dim3(2, 16, NTYPES), dim3(32, 8)>>>(W_in, Winhi, Winlo, FIN, HID);
    {
        const int xn4 = NTYPES * NNODES * FIN / 4;
        split_kernel<<<(xn4 + 255) / 256, 256>>>(x_all, xhi, xlo, xn4);
    }
    for (int t = 0; t < NTYPES; t++) {
        gemm_mma<1,0,0,64><<<ggt, 256, MS_TOTAL>>>(
            xhi + (size_t)t * NNODES * FIN, xlo + (size_t)t * NNODES * FIN,
            Winhi + (size_t)t * HID * FIN, Winlo + (size_t)t * HID * FIN,
            b_in + (size_t)t * HID, h + (size_t)t * TYPE_OFF, nullptr, nullptr, nullptr, NNODES);
    }
    cudaEventRecord(evLayer[0], 0);

    float* cur = h;
    float* nxt = h2;
    for (int l = 0; l < 2; l++) {
        // ---- side stream: prep all 6 edge types of this layer ----
        cudaStreamWaitEvent(s1, evLayer[l], 0);
        for (int t = 0; t < NET; t++) {
            const int s = ES[t], d = ED[t];
            float* aggT = agg + (size_t)t * TYPE_OFF;
            cudaMemsetAsync(aggT, 0, TYPE_OFF * sizeof(float), s1);
            scatter_add_kernel<<<NEDGE, 128, 0, s1>>>(cur + (size_t)s * TYPE_OFF,
                                                      edges + (size_t)t * 2 * NEDGE,
                                                      edges + (size_t)t * 2 * NEDGE + NEDGE,
                                                      aggT);
            split_add_kernel<<<(n4 + 255) / 256, 256, 0, s1>>>(
                aggT, cur + (size_t)d * TYPE_OFF,
                Ahi + (size_t)t * TYPE_OFF, Alo + (size_t)t * TYPE_OFF, n4);
            cudaEventRecord(evP[l][t], s1);
        }
        // ---- stream0: GEMM chain per edge type ----
        for (int t = 0; t < NET; t++) {
            const int d = ED[t];
            const size_t w = (size_t)l * NET + t;
            cudaStreamWaitEvent(0, evP[l][t], 0);
            gemm_mma<1,0,1,512><<<ggt, 256, MS_TOTAL>>>(
                Ahi + (size_t)t * TYPE_OFF, Alo + (size_t)t * TYPE_OFF,
                W1hi + w * WOFF, W1lo + w * WOFF, b1 + w * HID,
                nullptr, nullptr, Mhi, Mlo, NNODES);
            if (t == 1) {          // dst 0, partial (t=4 also hits dst 0)
                gemm_mma<0,0,0,512><<<ggt, 256, MS_TOTAL>>>(
                    Mhi, Mlo, W2hi + w * WOFF, W2lo + w * WOFF, b2 + w * HID,
                    tmp, nullptr, nullptr, nullptr, NNODES);
            } else if (t == 4) {   // dst 0, final: add tmp, relu
                gemm_mma<1,1,0,512><<<ggt, 256, MS_TOTAL>>>(
                    Mhi, Mlo, W2hi + w * WOFF, W2lo + w * WOFF, b2 + w * HID,
                    nxt + 0 * TYPE_OFF, tmp, nullptr, nullptr, NNODES);
            } else {               // single writer: relu directly
                gemm_mma<1,0,0,512><<<ggt, 256, MS_TOTAL>>>(
                    Mhi, Mlo, W2hi + w * WOFF, W2lo + w * WOFF, b2 + w * HID,
                    nxt + (size_t)d * TYPE_OFF, nullptr, nullptr, nullptr, NNODES);
            }
        }
        if (l == 0) cudaEventRecord(evLayer[1], 0);
        float* sw = cur; cur = nxt; nxt = sw;
    }

    // ---- output head on 'product' nodes (type 0) ----
    head_kernel<<<(NNODES * 32 + 255) / 256, 256>>>(cur, W_out, b_out, out, NNODES);
}

// round 6
// speedup vs baseline: 1.9752x; 1.0707x over previous
#include <cuda_runtime.h>
#include <cuda_bf16.h>
#include <cstdint>
#include <cstddef>

#define NNODES 20000
#define HID    512
#define NEDGE  160000
#define NTYPES 5
#define NET    6
#define FIN    64
#define NWMAT  12
#define TOFF   ((size_t)NNODES * HID)

// ---------------- scratch (__device__ globals; no allocs allowed) -------------
__device__ float g_h  [NTYPES * NNODES * HID];
__device__ float g_h2 [NTYPES * NNODES * HID];
__device__ float g_agg[NET * NNODES * HID];
__device__ float g_y1 [NNODES * HID];
__device__ float g_y4 [NNODES * HID];
__device__ __nv_bfloat16 g_Ahi[NET * NNODES * HID];
__device__ __nv_bfloat16 g_Alo[NET * NNODES * HID];
__device__ __nv_bfloat16 g_Mhi[NET * NNODES * HID];
__device__ __nv_bfloat16 g_Mlo[NET * NNODES * HID];
__device__ __nv_bfloat16 g_xhi[NTYPES * NNODES * FIN];
__device__ __nv_bfloat16 g_xlo[NTYPES * NNODES * FIN];
__device__ __nv_bfloat16 g_Winhi[NTYPES * HID * FIN];
__device__ __nv_bfloat16 g_Winlo[NTYPES * HID * FIN];
__device__ __nv_bfloat16 g_W1hi[NWMAT * HID * HID];
__device__ __nv_bfloat16 g_W1lo[NWMAT * HID * HID];
__device__ __nv_bfloat16 g_W2hi[NWMAT * HID * HID];
__device__ __nv_bfloat16 g_W2lo[NWMAT * HID * HID];

// EDGE_TYPES = ((4,1),(1,0),(0,2),(2,3),(3,0),(1,4))
__constant__ int c_ES[NET] = {4, 1, 0, 2, 3, 1};
__constant__ int c_ED[NET] = {1, 0, 2, 3, 0, 4};

// ---------------- family-common PTX helpers (sm_80+) --------------------------
__device__ __forceinline__ uint32_t smem_u32(const void* p) {
    uint32_t a;
    asm("{ .reg .u64 t; cvta.to.shared.u64 t, %1; cvt.u32.u64 %0, t; }" : "=r"(a) : "l"(p));
    return a;
}
__device__ __forceinline__ void cpasync16(uint32_t s, const void* g, int sz) {
    asm volatile("cp.async.cg.shared.global [%0], [%1], 16, %2;" :: "r"(s), "l"(g), "r"(sz));
}
__device__ __forceinline__ void cp_commit() { asm volatile("cp.async.commit_group;"); }
template<int N>
__device__ __forceinline__ void cp_wait() { asm volatile("cp.async.wait_group %0;" :: "n"(N)); }

__device__ __forceinline__ void ldsm4(uint32_t* r, uint32_t a) {
    asm volatile("ldmatrix.sync.aligned.m8n8.x4.shared.b16 {%0,%1,%2,%3}, [%4];"
                 : "=r"(r[0]), "=r"(r[1]), "=r"(r[2]), "=r"(r[3]) : "r"(a));
}
__device__ __forceinline__ void ldsm2(uint32_t* r, uint32_t a) {
    asm volatile("ldmatrix.sync.aligned.m8n8.x2.shared.b16 {%0,%1}, [%2];"
                 : "=r"(r[0]), "=r"(r[1]) : "r"(a));
}
__device__ __forceinline__ void mma16816(float* d, const uint32_t* a, const uint32_t* b) {
    asm volatile("mma.sync.aligned.m16n8k16.row.col.f32.bf16.bf16.f32 "
                 "{%0,%1,%2,%3}, {%4,%5,%6,%7}, {%8,%9}, {%0,%1,%2,%3};"
                 : "+f"(d[0]), "+f"(d[1]), "+f"(d[2]), "+f"(d[3])
                 : "r"(a[0]), "r"(a[1]), "r"(a[2]), "r"(a[3]), "r"(b[0]), "r"(b[1]));
}

// ---------------------------------------------------------------------
// Batched split-bf16 GEMM on mma.sync; blockIdx.z = batch index t.
// MODE 0: GEMM1  -> relu, bf16 hi/lo split out to Chi/Clo + t*TOFF
// MODE 1: GEMM2  -> t==1 raw->y1, t==4 raw->y4, else relu -> C + ED[t]*TOFF
// MODE 2: inproj -> relu -> C + t*TOFF
// CTA 128x128, BK=32, 8 warps, 3-stage cp.async; Ahi*Bhi + Ahi*Blo + Alo*Bhi.
// ---------------------------------------------------------------------
#define MS_A_HI 0
#define MS_A_LO 10240
#define MS_B_HI 20480
#define MS_B_LO 30720
#define MS_STAGE 40960
#define MS_TOTAL (3 * MS_STAGE)

template<int MODE, int LDK>
__global__ __launch_bounds__(256, 1)
void gemm_mma_b(const __nv_bfloat16* __restrict__ Ahi, const __nv_bfloat16* __restrict__ Alo,
                size_t aStride,
                const __nv_bfloat16* __restrict__ Whi, const __nv_bfloat16* __restrict__ Wlo,
                const float* __restrict__ bias,
                float* __restrict__ C,
                __nv_bfloat16* __restrict__ Chi, __nv_bfloat16* __restrict__ Clo,
                float* __restrict__ y1, float* __restrict__ y4,
                int M)
{
    constexpr int NKT = LDK / 32;
    extern __shared__ char smem[];
    const uint32_t sb = smem_u32(smem);
    const int t    = blockIdx.z;
    const int tid  = threadIdx.x;
    const int lane = tid & 31;
    const int wid  = tid >> 5;
    const int wm   = (wid >> 2) * 64;
    const int wn   = (wid & 3) * 32;
    const int bm   = blockIdx.x * 128;
    const int bn   = blockIdx.y * 128;

    Ahi += (size_t)t * aStride;
    Alo += (size_t)t * aStride;
    Whi += (size_t)t * (size_t)HID * LDK;
    Wlo += (size_t)t * (size_t)HID * LDK;
    bias += (size_t)t * HID;

    auto load_stage = [&](int st, int kt) {
        const int kc = kt * 32;
        const uint32_t sbase = sb + st * MS_STAGE;
#pragma unroll
        for (int j = 0; j < 2; ++j) {
            const int c   = tid + j * 256;
            const int row = c >> 2;
            const int c16 = c & 3;
            const uint32_t so = (uint32_t)(row * 80 + c16 * 16);
            const int gr = bm + row;
            const int sz = (gr < M) ? 16 : 0;
            const size_t ga = (size_t)gr * LDK + kc + c16 * 8;
            cpasync16(sbase + MS_A_HI + so, Ahi + ga, sz);
            cpasync16(sbase + MS_A_LO + so, Alo + ga, sz);
            const size_t gb = (size_t)(bn + row) * LDK + kc + c16 * 8;
            cpasync16(sbase + MS_B_HI + so, Whi + gb, 16);
            cpasync16(sbase + MS_B_LO + so, Wlo + gb, 16);
        }
        cp_commit();
    };

    float acc[4][4][4];
#pragma unroll
    for (int mi = 0; mi < 4; ++mi)
#pragma unroll
        for (int ni = 0; ni < 4; ++ni)
#pragma unroll
            for (int q = 0; q < 4; ++q) acc[mi][ni][q] = 0.f;

    load_stage(0, 0);
    if (NKT > 1) load_stage(1, 1);

    const uint32_t a_row = (uint32_t)(lane & 15);
    const uint32_t a_k16 = (uint32_t)((lane >> 4) * 16);
    const uint32_t b_row = (uint32_t)(lane & 7);
    const uint32_t b_k16 = (uint32_t)(((lane >> 3) & 1) * 16);

#pragma unroll 1
    for (int kt = 0; kt < NKT; ++kt) {
        if (kt >= NKT - 1) cp_wait<0>();
        else               cp_wait<1>();
        __syncthreads();
        if (kt + 2 < NKT) load_stage((kt + 2) % 3, kt + 2);

        const uint32_t sbase = sb + (uint32_t)(kt % 3) * MS_STAGE;
#pragma unroll
        for (int k2 = 0; k2 < 2; ++k2) {
            const uint32_t koff = (uint32_t)(k2 * 32);
            uint32_t ah[4][4], al[4][4], bh[4][2], bl[4][2];
#pragma unroll
            for (int mi = 0; mi < 4; ++mi) {
                uint32_t ad = sbase + (uint32_t)((wm + mi * 16 + a_row) * 80) + a_k16 + koff;
                ldsm4(ah[mi], ad + MS_A_HI);
                ldsm4(al[mi], ad + MS_A_LO);
            }
#pragma unroll
            for (int ni = 0; ni < 4; ++ni) {
                uint32_t bd = sbase + (uint32_t)((wn + ni * 8 + b_row) * 80) + b_k16 + koff;
                ldsm2(bh[ni], bd + MS_B_HI);
                ldsm2(bl[ni], bd + MS_B_LO);
            }
#pragma unroll
            for (int mi = 0; mi < 4; ++mi)
#pragma unroll
                for (int ni = 0; ni < 4; ++ni) {
                    mma16816(acc[mi][ni], ah[mi], bh[ni]);
                    mma16816(acc[mi][ni], ah[mi], bl[ni]);
                    mma16816(acc[mi][ni], al[mi], bh[ni]);
                }
        }
    }

    // ---- per-mode output routing ----
    float* Cout = nullptr;
    bool doRelu = true;
    if (MODE == 0) {
        Chi += (size_t)t * TOFF;
        Clo += (size_t)t * TOFF;
    } else if (MODE == 1) {
        const int d = c_ED[t];
        if (t == 1)      { Cout = y1; doRelu = false; }
        else if (t == 4) { Cout = y4; doRelu = false; }
        else             { Cout = C + (size_t)d * TOFF; }
    } else {
        Cout = C + (size_t)t * TOFF;
    }

#pragma unroll
    for (int mi = 0; mi < 4; ++mi) {
        const int r0 = bm + wm + mi * 16 + (lane >> 2);
#pragma unroll
        for (int half = 0; half < 2; ++half) {
            const int r = r0 + half * 8;
            if (r >= M) continue;
#pragma unroll
            for (int ni = 0; ni < 4; ++ni) {
                const int c = wn + ni * 8 + (lane & 3) * 2 + bn;
                float v0 = acc[mi][ni][half * 2 + 0] + bias[c];
                float v1 = acc[mi][ni][half * 2 + 1] + bias[c + 1];
                if (MODE == 0) {
                    v0 = fmaxf(v0, 0.f); v1 = fmaxf(v1, 0.f);
                    __nv_bfloat16 h0 = __float2bfloat16(v0), h1 = __float2bfloat16(v1);
                    float l0 = v0 - __bfloat162float(h0);
                    float l1 = v1 - __bfloat162float(h1);
                    __nv_bfloat16 q0 = __float2bfloat16(l0), q1 = __float2bfloat16(l1);
                    uint32_t hp = ((uint32_t)__bfloat16_as_ushort(h1) << 16) | __bfloat16_as_ushort(h0);
                    uint32_t lp = ((uint32_t)__bfloat16_as_ushort(q1) << 16) | __bfloat16_as_ushort(q0);
                    *(uint32_t*)(Chi + (size_t)r * HID + c) = hp;
                    *(uint32_t*)(Clo + (size_t)r * HID + c) = lp;
                } else {
                    if (doRelu) { v0 = fmaxf(v0, 0.f); v1 = fmaxf(v1, 0.f); }
                    *(float2*)(Cout + (size_t)r * HID + c) = make_float2(v0, v1);
                }
            }
        }
    }
}

// ---------------------------------------------------------------------
// Batched edge scatter over all 6 edge types: blockIdx.y = t.
__global__ void scatter_b(const float* __restrict__ cur,
                          const int* __restrict__ edges,
                          float* __restrict__ agg)
{
    const int t = blockIdx.y;
    const int e = blockIdx.x;
    const int* srcI = edges + (size_t)t * 2 * NEDGE;
    const int s = srcI[e];
    const int d = srcI[NEDGE + e];
    const float* hs = cur + (size_t)c_ES[t] * TOFF + (size_t)s * HID;
    float* p = agg + (size_t)t * TOFF + (size_t)d * HID + threadIdx.x * 4;
    float4 v = *(const float4*)(hs + threadIdx.x * 4);
    asm volatile("red.global.add.v4.f32 [%0], {%1, %2, %3, %4};"
                 :: "l"(p), "f"(v.x), "f"(v.y), "f"(v.z), "f"(v.w) : "memory");
}

// Batched (agg[t] + h[ED[t]]) -> bf16 hi/lo ; blockIdx.y = t.
__global__ void split_add_b(const float* __restrict__ agg, const float* __restrict__ cur,
                            __nv_bfloat16* __restrict__ hi, __nv_bfloat16* __restrict__ lo,
                            int n4)
{
    const int t = blockIdx.y;
    int i = blockIdx.x * blockDim.x + threadIdx.x;
    if (i >= n4) return;
    float4 va = ((const float4*)(agg + (size_t)t * TOFF))[i];
    float4 vb = ((const float4*)(cur + (size_t)c_ED[t] * TOFF))[i];
    float x0 = va.x + vb.x, x1 = va.y + vb.y, x2 = va.z + vb.z, x3 = va.w + vb.w;
    __nv_bfloat16 h0 = __float2bfloat16(x0), h1 = __float2bfloat16(x1);
    __nv_bfloat16 h2 = __float2bfloat16(x2), h3 = __float2bfloat16(x3);
    __nv_bfloat16 l0 = __float2bfloat16(x0 - __bfloat162float(h0));
    __nv_bfloat16 l1 = __float2bfloat16(x1 - __bfloat162float(h1));
    __nv_bfloat16 l2 = __float2bfloat16(x2 - __bfloat162float(h2));
    __nv_bfloat16 l3 = __float2bfloat16(x3 - __bfloat162float(h3));
    uint2 hv, lv;
    hv.x = ((uint32_t)__bfloat16_as_ushort(h1) << 16) | __bfloat16_as_ushort(h0);
    hv.y = ((uint32_t)__bfloat16_as_ushort(h3) << 16) | __bfloat16_as_ushort(h2);
    lv.x = ((uint32_t)__bfloat16_as_ushort(l1) << 16) | __bfloat16_as_ushort(l0);
    lv.y = ((uint32_t)__bfloat16_as_ushort(l3) << 16) | __bfloat16_as_ushort(l2);
    ((uint2*)(hi + (size_t)t * TOFF))[i] = hv;
    ((uint2*)(lo + (size_t)t * TOFF))[i] = lv;
}

__global__ void split_kernel(const float* __restrict__ a,
                             __nv_bfloat16* __restrict__ hi, __nv_bfloat16* __restrict__ lo,
                             int n4)
{
    int i = blockIdx.x * blockDim.x + threadIdx.x;
    if (i >= n4) return;
    float4 va = ((const float4*)a)[i];
    __nv_bfloat16 h0 = __float2bfloat16(va.x), h1 = __float2bfloat16(va.y);
    __nv_bfloat16 h2 = __float2bfloat16(va.z), h3 = __float2bfloat16(va.w);
    __nv_bfloat16 l0 = __float2bfloat16(va.x - __bfloat162float(h0));
    __nv_bfloat16 l1 = __float2bfloat16(va.y - __bfloat162float(h1));
    __nv_bfloat16 l2 = __float2bfloat16(va.z - __bfloat162float(h2));
    __nv_bfloat16 l3 = __float2bfloat16(va.w - __bfloat162float(h3));
    uint2 hv, lv;
    hv.x = ((uint32_t)__bfloat16_as_ushort(h1) << 16) | __bfloat16_as_ushort(h0);
    hv.y = ((uint32_t)__bfloat16_as_ushort(h3) << 16) | __bfloat16_as_ushort(h2);
    lv.x = ((uint32_t)__bfloat16_as_ushort(l1) << 16) | __bfloat16_as_ushort(l0);
    lv.y = ((uint32_t)__bfloat16_as_ushort(l3) << 16) | __bfloat16_as_ushort(l2);
    ((uint2*)hi)[i] = hv;
    ((uint2*)lo)[i] = lv;
}

// combine dst-0: out = relu(y1 + y4)
__global__ void combine0_kernel(const float* __restrict__ y1, const float* __restrict__ y4,
                                float* __restrict__ o, int n4)
{
    int i = blockIdx.x * blockDim.x + threadIdx.x;
    if (i >= n4) return;
    float4 a = ((const float4*)y1)[i];
    float4 b = ((const float4*)y4)[i];
    float4 v;
    v.x = fmaxf(a.x + b.x, 0.f);
    v.y = fmaxf(a.y + b.y, 0.f);
    v.z = fmaxf(a.z + b.z, 0.f);
    v.w = fmaxf(a.w + b.w, 0.f);
    ((float4*)o)[i] = v;
}

// transpose + split weights: W[m][Kd][Nd] fp32 -> Wt_hi/lo[m][Nd][Kd] bf16
__global__ void wconv_kernel(const float* __restrict__ W,
                             __nv_bfloat16* __restrict__ Whi, __nv_bfloat16* __restrict__ Wlo,
                             int Kd, int Nd)
{
    __shared__ float t[32][33];
    const int m = blockIdx.z;
    const int k0 = blockIdx.x * 32, n0 = blockIdx.y * 32;
    const int tx = threadIdx.x, ty = threadIdx.y;
    const float* Wm = W + (size_t)m * Kd * Nd;
#pragma unroll
    for (int i = 0; i < 4; i++)
        t[ty + i * 8][tx] = Wm[(size_t)(k0 + ty + i * 8) * Nd + n0 + tx];
    __syncthreads();
    const size_t ob = (size_t)m * Kd * Nd;
#pragma unroll
    for (int i = 0; i < 4; i++) {
        int n = n0 + ty + i * 8, k = k0 + tx;
        float v = t[tx][ty + i * 8];
        __nv_bfloat16 h = __float2bfloat16(v);
        Whi[ob + (size_t)n * Kd + k] = h;
        Wlo[ob + (size_t)n * Kd + k] = __float2bfloat16(v - __bfloat162float(h));
    }
}

// ---------------------------------------------------------------------
__global__ void head_kernel(const float* __restrict__ h0, const float* __restrict__ Wout,
                            const float* __restrict__ bout, float* __restrict__ out, int M)
{
    const int gw = (int)((blockIdx.x * (size_t)blockDim.x + threadIdx.x) >> 5);
    const int lane = threadIdx.x & 31;
    if (gw >= M) return;
    const float* row = h0 + (size_t)gw * HID;
    float s = 0.f;
#pragma unroll
    for (int i = 0; i < 4; i++) {
        int c = (lane + i * 32) * 4;
        float4 a = *(const float4*)(row + c);
        float4 w = *(const float4*)(Wout + c);
        s += a.x * w.x + a.y * w.y + a.z * w.z + a.w * w.w;
    }
#pragma unroll
    for (int o = 16; o; o >>= 1) s += __shfl_xor_sync(0xffffffffu, s, o);
    if (lane == 0) out[gw] = s + bout[0];
}

// ---------------------------------------------------------------------
extern "C" void kernel_launch(void* const* d_in, const int* in_sizes, int n_in,
                              void* d_out, int out_size)
{
    const float* x_all = (const float*)d_in[0];
    const float* W_in  = (const float*)d_in[1];
    const float* b_in  = (const float*)d_in[2];
    const float* W1    = (const float*)d_in[3];
    const float* b1    = (const float*)d_in[4];
    const float* W2    = (const float*)d_in[5];
    const float* b2    = (const float*)d_in[6];
    const float* W_out = (const float*)d_in[7];
    const float* b_out = (const float*)d_in[8];
    const int*   edges = (const int*)d_in[9];
    float* out = (float*)d_out;

    float *h, *h2, *agg, *y1, *y4;
    __nv_bfloat16 *Ahi, *Alo, *Mhi, *Mlo, *xhi, *xlo, *Winhi, *Winlo, *W1hi, *W1lo, *W2hi, *W2lo;
    cudaGetSymbolAddress((void**)&h,    g_h);
    cudaGetSymbolAddress((void**)&h2,   g_h2);
    cudaGetSymbolAddress((void**)&agg,  g_agg);
    cudaGetSymbolAddress((void**)&y1,   g_y1);
    cudaGetSymbolAddress((void**)&y4,   g_y4);
    cudaGetSymbolAddress((void**)&Ahi,  g_Ahi);
    cudaGetSymbolAddress((void**)&Alo,  g_Alo);
    cudaGetSymbolAddress((void**)&Mhi,  g_Mhi);
    cudaGetSymbolAddress((void**)&Mlo,  g_Mlo);
    cudaGetSymbolAddress((void**)&xhi,  g_xhi);
    cudaGetSymbolAddress((void**)&xlo,  g_xlo);
    cudaGetSymbolAddress((void**)&Winhi, g_Winhi);
    cudaGetSymbolAddress((void**)&Winlo, g_Winlo);
    cudaGetSymbolAddress((void**)&W1hi, g_W1hi);
    cudaGetSymbolAddress((void**)&W1lo, g_W1lo);
    cudaGetSymbolAddress((void**)&W2hi, g_W2hi);
    cudaGetSymbolAddress((void**)&W2lo, g_W2lo);

    cudaFuncSetAttribute(gemm_mma_b<0,512>, cudaFuncAttributeMaxDynamicSharedMemorySize, MS_TOTAL);
    cudaFuncSetAttribute(gemm_mma_b<1,512>, cudaFuncAttributeMaxDynamicSharedMemorySize, MS_TOTAL);
    cudaFuncSetAttribute(gemm_mma_b<2,64>,  cudaFuncAttributeMaxDynamicSharedMemorySize, MS_TOTAL);

    const size_t WOFF = (size_t)HID * HID;
    const int gx = (NNODES + 127) / 128;
    const int n4 = NNODES * HID / 4;
    const int nb = (n4 + 255) / 256;

    // ---- weight prep + input split ----
    wconv_kernel<<<dim3(16, 16, NWMAT), dim3(32, 8)>>>(W1, W1hi, W1lo, HID, HID);
    wconv_kernel<<<dim3(16, 16, NWMAT), dim3(32, 8)>>>(W2, W2hi, W2lo, HID, HID);
    wconv_kernel<<<dim3(2, 16, NTYPES), dim3(32, 8)>>>(W_in, Winhi, Winlo, FIN, HID);
    {
        const int xn4 = NTYPES * NNODES * FIN / 4;
        split_kernel<<<(xn4 + 255) / 256, 256>>>(x_all, xhi, xlo, xn4);
    }

    // ---- input projection: all 5 types in one batched launch ----
    gemm_mma_b<2,64><<<dim3(gx, 4, NTYPES), 256, MS_TOTAL>>>(
        xhi, xlo, (size_t)NNODES * FIN, Winhi, Winlo, b_in,
        h, nullptr, nullptr, nullptr, nullptr, NNODES);

    float* cur = h;
    float* nxt = h2;
    for (int l = 0; l < 2; l++) {
        // prep all 6 edge types (batched)
        cudaMemsetAsync(agg, 0, (size_t)NET * TOFF * sizeof(float));
        scatter_b<<<dim3(NEDGE, NET), 128>>>(cur, edges, agg);
        split_add_b<<<dim3(nb, NET), 256>>>(agg, cur, Ahi, Alo, n4);
        // GEMM1 for all 6 types (batched): M[t] = relu(A[t] @ W1[l,t] + b1) -> hi/lo
        gemm_mma_b<0,512><<<dim3(gx, 4, NET), 256, MS_TOTAL>>>(
            Ahi, Alo, TOFF, W1hi + (size_t)l * NET * WOFF, W1lo + (size_t)l * NET * WOFF,
            b1 + (size_t)l * NET * HID, nullptr, Mhi, Mlo, nullptr, nullptr, NNODES);
        // GEMM2 for all 6 types (batched) with dst routing
        gemm_mma_b<1,512><<<dim3(gx, 4, NET), 256, MS_TOTAL>>>(
            Mhi, Mlo, TOFF, W2hi + (size_t)l * NET * WOFF, W2lo + (size_t)l * NET * WOFF,
            b2 + (size_t)l * NET * HID, nxt, nullptr, nullptr, y1, y4, NNODES);
        // dst 0 had two writers: combine
        combine0_kernel<<<nb, 256>>>(y1, y4, nxt, n4);
        float* sw = cur; cur = nxt; nxt = sw;
    }

    // ---- output head on 'product' nodes (type 0) ----
    head_kernel<<<(NNODES * 32 + 255) / 256, 256>>>(cur, W_out, b_out, out, NNODES);
}

// round 7
// speedup vs baseline: 2.5304x; 1.2811x over previous
#include <cuda_runtime.h>
#include <cuda_bf16.h>
#include <cstdint>
#include <cstddef>

#define NNODES 20000
#define HID    512
#define NEDGE  160000
#define NTYPES 5
#define NET    6
#define FIN    64
#define NWMAT  12
#define TOFF   ((size_t)NNODES * HID)

// ---------------- scratch (__device__ globals; no allocs allowed) -------------
__device__ float g_h  [NTYPES * NNODES * HID];
__device__ float g_h2 [NTYPES * NNODES * HID];
__device__ float g_y1 [NNODES * HID];
__device__ float g_y4 [NNODES * HID];
__device__ __nv_bfloat16 g_Ahi[NET * NNODES * HID];
__device__ __nv_bfloat16 g_Alo[NET * NNODES * HID];
__device__ __nv_bfloat16 g_Mhi[NET * NNODES * HID];
__device__ __nv_bfloat16 g_Mlo[NET * NNODES * HID];
__device__ __nv_bfloat16 g_xhi[NTYPES * NNODES * FIN];
__device__ __nv_bfloat16 g_xlo[NTYPES * NNODES * FIN];
__device__ __nv_bfloat16 g_Winhi[NTYPES * HID * FIN];
__device__ __nv_bfloat16 g_Winlo[NTYPES * HID * FIN];
__device__ __nv_bfloat16 g_W1hi[NWMAT * HID * HID];
__device__ __nv_bfloat16 g_W1lo[NWMAT * HID * HID];
__device__ __nv_bfloat16 g_W2hi[NWMAT * HID * HID];
__device__ __nv_bfloat16 g_W2lo[NWMAT * HID * HID];
// CSR scratch
__device__ int g_cnt [NET * NNODES];
__device__ int g_off [NET * (NNODES + 1)];
__device__ int g_curp[NET * NNODES];
__device__ int g_eidx[NET * NEDGE];

// EDGE_TYPES = ((4,1),(1,0),(0,2),(2,3),(3,0),(1,4))
__constant__ int c_ES[NET] = {4, 1, 0, 2, 3, 1};
__constant__ int c_ED[NET] = {1, 0, 2, 3, 0, 4};

// ---------------- family-common PTX helpers (sm_80+) --------------------------
__device__ __forceinline__ uint32_t smem_u32(const void* p) {
    uint32_t a;
    asm("{ .reg .u64 t; cvta.to.shared.u64 t, %1; cvt.u32.u64 %0, t; }" : "=r"(a) : "l"(p));
    return a;
}
__device__ __forceinline__ void cpasync16(uint32_t s, const void* g, int sz) {
    asm volatile("cp.async.cg.shared.global [%0], [%1], 16, %2;" :: "r"(s), "l"(g), "r"(sz));
}
__device__ __forceinline__ void cp_commit() { asm volatile("cp.async.commit_group;"); }
template<int N>
__device__ __forceinline__ void cp_wait() { asm volatile("cp.async.wait_group %0;" :: "n"(N)); }

__device__ __forceinline__ void ldsm4(uint32_t* r, uint32_t a) {
    asm volatile("ldmatrix.sync.aligned.m8n8.x4.shared.b16 {%0,%1,%2,%3}, [%4];"
                 : "=r"(r[0]), "=r"(r[1]), "=r"(r[2]), "=r"(r[3]) : "r"(a));
}
__device__ __forceinline__ void ldsm2(uint32_t* r, uint32_t a) {
    asm volatile("ldmatrix.sync.aligned.m8n8.x2.shared.b16 {%0,%1}, [%2];"
                 : "=r"(r[0]), "=r"(r[1]) : "r"(a));
}
__device__ __forceinline__ void mma16816(float* d, const uint32_t* a, const uint32_t* b) {
    asm volatile("mma.sync.aligned.m16n8k16.row.col.f32.bf16.bf16.f32 "
                 "{%0,%1,%2,%3}, {%4,%5,%6,%7}, {%8,%9}, {%0,%1,%2,%3};"
                 : "+f"(d[0]), "+f"(d[1]), "+f"(d[2]), "+f"(d[3])
                 : "r"(a[0]), "r"(a[1]), "r"(a[2]), "r"(a[3]), "r"(b[0]), "r"(b[1]));
}

// ---------------------------------------------------------------------
// Batched split-bf16 GEMM on mma.sync; blockIdx.z = batch index t.
// MODE 0: GEMM1  -> relu, bf16 hi/lo split out to Chi/Clo + t*TOFF
// MODE 1: GEMM2  -> t==1 raw->y1, t==4 raw->y4, else relu -> C + ED[t]*TOFF
// MODE 2: inproj -> relu -> C + t*TOFF
// CTA 128x128, BK=32, 8 warps, 3-stage cp.async; Ahi*Bhi + Ahi*Blo + Alo*Bhi.
// (measured at the sm_103 legacy-HMMA throughput cap)
// ---------------------------------------------------------------------
#define MS_A_HI 0
#define MS_A_LO 10240
#define MS_B_HI 20480
#define MS_B_LO 30720
#define MS_STAGE 40960
#define MS_TOTAL (3 * MS_STAGE)

template<int MODE, int LDK>
__global__ __launch_bounds__(256, 1)
void gemm_mma_b(const __nv_bfloat16* __restrict__ Ahi, const __nv_bfloat16* __restrict__ Alo,
                size_t aStride,
                const __nv_bfloat16* __restrict__ Whi, const __nv_bfloat16* __restrict__ Wlo,
                const float* __restrict__ bias,
                float* __restrict__ C,
                __nv_bfloat16* __restrict__ Chi, __nv_bfloat16* __restrict__ Clo,
                float* __restrict__ y1, float* __restrict__ y4,
                int M)
{
    constexpr int NKT = LDK / 32;
    extern __shared__ char smem[];
    const uint32_t sb = smem_u32(smem);
    const int t    = blockIdx.z;
    const int tid  = threadIdx.x;
    const int lane = tid & 31;
    const int wid  = tid >> 5;
    const int wm   = (wid >> 2) * 64;
    const int wn   = (wid & 3) * 32;
    const int bm   = blockIdx.x * 128;
    const int bn   = blockIdx.y * 128;

    Ahi += (size_t)t * aStride;
    Alo += (size_t)t * aStride;
    Whi += (size_t)t * (size_t)HID * LDK;
    Wlo += (size_t)t * (size_t)HID * LDK;
    bias += (size_t)t * HID;

    auto load_stage = [&](int st, int kt) {
        const int kc = kt * 32;
        const uint32_t sbase = sb + st * MS_STAGE;
#pragma unroll
        for (int j = 0; j < 2; ++j) {
            const int c   = tid + j * 256;
            const int row = c >> 2;
            const int c16 = c & 3;
            const uint32_t so = (uint32_t)(row * 80 + c16 * 16);
            const int gr = bm + row;
            const int sz = (gr < M) ? 16 : 0;
            const size_t ga = (size_t)gr * LDK + kc + c16 * 8;
            cpasync16(sbase + MS_A_HI + so, Ahi + ga, sz);
            cpasync16(sbase + MS_A_LO + so, Alo + ga, sz);
            const size_t gb = (size_t)(bn + row) * LDK + kc + c16 * 8;
            cpasync16(sbase + MS_B_HI + so, Whi + gb, 16);
            cpasync16(sbase + MS_B_LO + so, Wlo + gb, 16);
        }
        cp_commit();
    };

    float acc[4][4][4];
#pragma unroll
    for (int mi = 0; mi < 4; ++mi)
#pragma unroll
        for (int ni = 0; ni < 4; ++ni)
#pragma unroll
            for (int q = 0; q < 4; ++q) acc[mi][ni][q] = 0.f;

    load_stage(0, 0);
    if (NKT > 1) load_stage(1, 1);

    const uint32_t a_row = (uint32_t)(lane & 15);
    const uint32_t a_k16 = (uint32_t)((lane >> 4) * 16);
    const uint32_t b_row = (uint32_t)(lane & 7);
    const uint32_t b_k16 = (uint32_t)(((lane >> 3) & 1) * 16);

#pragma unroll 1
    for (int kt = 0; kt < NKT; ++kt) {
        if (kt >= NKT - 1) cp_wait<0>();
        else               cp_wait<1>();
        __syncthreads();
        if (kt + 2 < NKT) load_stage((kt + 2) % 3, kt + 2);

        const uint32_t sbase = sb + (uint32_t)(kt % 3) * MS_STAGE;
#pragma unroll
        for (int k2 = 0; k2 < 2; ++k2) {
            const uint32_t koff = (uint32_t)(k2 * 32);
            uint32_t ah[4][4], al[4][4], bh[4][2], bl[4][2];
#pragma unroll
            for (int mi = 0; mi < 4; ++mi) {
                uint32_t ad = sbase + (uint32_t)((wm + mi * 16 + a_row) * 80) + a_k16 + koff;
                ldsm4(ah[mi], ad + MS_A_HI);
                ldsm4(al[mi], ad + MS_A_LO);
            }
#pragma unroll
            for (int ni = 0; ni < 4; ++ni) {
                uint32_t bd = sbase + (uint32_t)((wn + ni * 8 + b_row) * 80) + b_k16 + koff;
                ldsm2(bh[ni], bd + MS_B_HI);
                ldsm2(bl[ni], bd + MS_B_LO);
            }
#pragma unroll
            for (int mi = 0; mi < 4; ++mi)
#pragma unroll
                for (int ni = 0; ni < 4; ++ni) {
                    mma16816(acc[mi][ni], ah[mi], bh[ni]);
                    mma16816(acc[mi][ni], ah[mi], bl[ni]);
                    mma16816(acc[mi][ni], al[mi], bh[ni]);
                }
        }
    }

    // ---- per-mode output routing ----
    float* Cout = nullptr;
    bool doRelu = true;
    if (MODE == 0) {
        Chi += (size_t)t * TOFF;
        Clo += (size_t)t * TOFF;
    } else if (MODE == 1) {
        const int d = c_ED[t];
        if (t == 1)      { Cout = y1; doRelu = false; }
        else if (t == 4) { Cout = y4; doRelu = false; }
        else             { Cout = C + (size_t)d * TOFF; }
    } else {
        Cout = C + (size_t)t * TOFF;
    }

#pragma unroll
    for (int mi = 0; mi < 4; ++mi) {
        const int r0 = bm + wm + mi * 16 + (lane >> 2);
#pragma unroll
        for (int half = 0; half < 2; ++half) {
            const int r = r0 + half * 8;
            if (r >= M) continue;
#pragma unroll
            for (int ni = 0; ni < 4; ++ni) {
                const int c = wn + ni * 8 + (lane & 3) * 2 + bn;
                float v0 = acc[mi][ni][half * 2 + 0] + bias[c];
                float v1 = acc[mi][ni][half * 2 + 1] + bias[c + 1];
                if (MODE == 0) {
                    v0 = fmaxf(v0, 0.f); v1 = fmaxf(v1, 0.f);
                    __nv_bfloat16 h0 = __float2bfloat16(v0), h1 = __float2bfloat16(v1);
                    float l0 = v0 - __bfloat162float(h0);
                    float l1 = v1 - __bfloat162float(h1);
                    __nv_bfloat16 q0 = __float2bfloat16(l0), q1 = __float2bfloat16(l1);
                    uint32_t hp = ((uint32_t)__bfloat16_as_ushort(h1) << 16) | __bfloat16_as_ushort(h0);
                    uint32_t lp = ((uint32_t)__bfloat16_as_ushort(q1) << 16) | __bfloat16_as_ushort(q0);
                    *(uint32_t*)(Chi + (size_t)r * HID + c) = hp;
                    *(uint32_t*)(Clo + (size_t)r * HID + c) = lp;
                } else {
                    if (doRelu) { v0 = fmaxf(v0, 0.f); v1 = fmaxf(v1, 0.f); }
                    *(float2*)(Cout + (size_t)r * HID + c) = make_float2(v0, v1);
                }
            }
        }
    }
}

// ---------------------------------------------------------------------
// CSR build: histogram -> per-type exclusive scan -> fill
// ---------------------------------------------------------------------
__global__ void hist_kernel(const int* __restrict__ edges, int* __restrict__ cnt)
{
    const int i = blockIdx.x * blockDim.x + threadIdx.x;
    if (i >= NET * NEDGE) return;
    const int t = i / NEDGE, e = i - t * NEDGE;
    const int d = edges[(size_t)t * 2 * NEDGE + NEDGE + e];
    atomicAdd(&cnt[t * NNODES + d], 1);
}

__global__ void scan_kernel(const int* __restrict__ cnt, int* __restrict__ off,
                            int* __restrict__ curp)
{
    const int t = blockIdx.x;
    const int tid = threadIdx.x;
    const int lane = tid & 31, wid = tid >> 5;
    __shared__ int wsum[32];
    __shared__ int chunkTotal;
    int carry = 0;
    for (int base = 0; base < NNODES; base += 1024) {
        const int idx = base + tid;
        int v = (idx < NNODES) ? cnt[t * NNODES + idx] : 0;
        // intra-warp inclusive scan
        int x = v;
#pragma unroll
        for (int o = 1; o < 32; o <<= 1) {
            int y = __shfl_up_sync(0xffffffffu, x, o);
            if (lane >= o) x += y;
        }
        if (lane == 31) wsum[wid] = x;
        __syncthreads();
        if (wid == 0) {
            int w = wsum[lane];
#pragma unroll
            for (int o = 1; o < 32; o <<= 1) {
                int y = __shfl_up_sync(0xffffffffu, w, o);
                if (lane >= o) w += y;
            }
            wsum[lane] = w;
            if (lane == 31) chunkTotal = w;
        }
        __syncthreads();
        const int incl = x + (wid > 0 ? wsum[wid - 1] : 0);
        const int excl = carry + incl - v;
        if (idx < NNODES) {
            off[t * (NNODES + 1) + idx] = excl;
            curp[t * NNODES + idx] = excl;
        }
        carry += chunkTotal;
        __syncthreads();
    }
    if (tid == 0) off[t * (NNODES + 1) + NNODES] = carry;
}

__global__ void fill_kernel(const int* __restrict__ edges, int* __restrict__ curp,
                            int* __restrict__ eidx)
{
    const int i = blockIdx.x * blockDim.x + threadIdx.x;
    if (i >= NET * NEDGE) return;
    const int t = i / NEDGE, e = i - t * NEDGE;
    const int s = edges[(size_t)t * 2 * NEDGE + e];
    const int d = edges[(size_t)t * 2 * NEDGE + NEDGE + e];
    const int p = atomicAdd(&curp[t * NNODES + d], 1);
    eidx[t * NEDGE + p] = s;
}

// ---------------------------------------------------------------------
// Fused GIN aggregation via CSR gather + bf16 hi/lo split.
// block = (dst row, edge type); 128 threads each own 4 floats of the row.
// A[t][d] = h[ED[t]][d] + sum_{s in N_t(d)} h[ES[t]][s]   -> Ahi/Alo
// ---------------------------------------------------------------------
__global__ __launch_bounds__(128)
void gather_split_kernel(const float* __restrict__ hcur,
                         const int* __restrict__ off, const int* __restrict__ eidx,
                         __nv_bfloat16* __restrict__ Ahi, __nv_bfloat16* __restrict__ Alo)
{
    const int d = blockIdx.x;
    const int t = blockIdx.y;
    const int c4 = threadIdx.x * 4;
    const int o0 = off[t * (NNODES + 1) + d];
    const int o1 = off[t * (NNODES + 1) + d + 1];
    const float* hsrc = hcur + (size_t)c_ES[t] * TOFF;
    const int* ei = eidx + (size_t)t * NEDGE;

    float4 acc = *(const float4*)(hcur + (size_t)c_ED[t] * TOFF + (size_t)d * HID + c4);
    for (int e = o0; e < o1; ++e) {
        const int s = __ldg(&ei[e]);
        const float4 v = *(const float4*)(hsrc + (size_t)s * HID + c4);
        acc.x += v.x; acc.y += v.y; acc.z += v.z; acc.w += v.w;
    }
    __nv_bfloat16 h0 = __float2bfloat16(acc.x), h1 = __float2bfloat16(acc.y);
    __nv_bfloat16 h2 = __float2bfloat16(acc.z), h3 = __float2bfloat16(acc.w);
    __nv_bfloat16 l0 = __float2bfloat16(acc.x - __bfloat162float(h0));
    __nv_bfloat16 l1 = __float2bfloat16(acc.y - __bfloat162float(h1));
    __nv_bfloat16 l2 = __float2bfloat16(acc.z - __bfloat162float(h2));
    __nv_bfloat16 l3 = __float2bfloat16(acc.w - __bfloat162float(h3));
    uint2 hv, lv;
    hv.x = ((uint32_t)__bfloat16_as_ushort(h1) << 16) | __bfloat16_as_ushort(h0);
    hv.y = ((uint32_t)__bfloat16_as_ushort(h3) << 16) | __bfloat16_as_ushort(h2);
    lv.x = ((uint32_t)__bfloat16_as_ushort(l1) << 16) | __bfloat16_as_ushort(l0);
    lv.y = ((uint32_t)__bfloat16_as_ushort(l3) << 16) | __bfloat16_as_ushort(l2);
    *(uint2*)(Ahi + (size_t)t * TOFF + (size_t)d * HID + c4) = hv;
    *(uint2*)(Alo + (size_t)t * TOFF + (size_t)d * HID + c4) = lv;
}

// ---------------------------------------------------------------------
__global__ void split_kernel(const float* __restrict__ a,
                             __nv_bfloat16* __restrict__ hi, __nv_bfloat16* __restrict__ lo,
                             int n4)
{
    int i = blockIdx.x * blockDim.x + threadIdx.x;
    if (i >= n4) return;
    float4 va = ((const float4*)a)[i];
    __nv_bfloat16 h0 = __float2bfloat16(va.x), h1 = __float2bfloat16(va.y);
    __nv_bfloat16 h2 = __float2bfloat16(va.z), h3 = __float2bfloat16(va.w);
    __nv_bfloat16 l0 = __float2bfloat16(va.x - __bfloat162float(h0));
    __nv_bfloat16 l1 = __float2bfloat16(va.y - __bfloat162float(h1));
    __nv_bfloat16 l2 = __float2bfloat16(va.z - __bfloat162float(h2));
    __nv_bfloat16 l3 = __float2bfloat16(va.w - __bfloat162float(h3));
    uint2 hv, lv;
    hv.x = ((uint32_t)__bfloat16_as_ushort(h1) << 16) | __bfloat16_as_ushort(h0);
    hv.y = ((uint32_t)__bfloat16_as_ushort(h3) << 16) | __bfloat16_as_ushort(h2);
    lv.x = ((uint32_t)__bfloat16_as_ushort(l1) << 16) | __bfloat16_as_ushort(l0);
    lv.y = ((uint32_t)__bfloat16_as_ushort(l3) << 16) | __bfloat16_as_ushort(l2);
    ((uint2*)hi)[i] = hv;
    ((uint2*)lo)[i] = lv;
}

// combine dst-0: out = relu(y1 + y4)
__global__ void combine0_kernel(const float* __restrict__ y1, const float* __restrict__ y4,
                                float* __restrict__ o, int n4)
{
    int i = blockIdx.x * blockDim.x + threadIdx.x;
    if (i >= n4) return;
    float4 a = ((const float4*)y1)[i];
    float4 b = ((const float4*)y4)[i];
    float4 v;
    v.x = fmaxf(a.x + b.x, 0.f);
    v.y = fmaxf(a.y + b.y, 0.f);
    v.z = fmaxf(a.z + b.z, 0.f);
    v.w = fmaxf(a.w + b.w, 0.f);
    ((float4*)o)[i] = v;
}

// transpose + split weights: W[m][Kd][Nd] fp32 -> Wt_hi/lo[m][Nd][Kd] bf16
__global__ void wconv_kernel(const float* __restrict__ W,
                             __nv_bfloat16* __restrict__ Whi, __nv_bfloat16* __restrict__ Wlo,
                             int Kd, int Nd)
{
    __shared__ float t[32][33];
    const int m = blockIdx.z;
    const int k0 = blockIdx.x * 32, n0 = blockIdx.y * 32;
    const int tx = threadIdx.x, ty = threadIdx.y;
    const float* Wm = W + (size_t)m * Kd * Nd;
#pragma unroll
    for (int i = 0; i < 4; i++)
        t[ty + i * 8][tx] = Wm[(size_t)(k0 + ty + i * 8) * Nd + n0 + tx];
    __syncthreads();
    const size_t ob = (size_t)m * Kd * Nd;
#pragma unroll
    for (int i = 0; i < 4; i++) {
        int n = n0 + ty + i * 8, k = k0 + tx;
        float v = t[tx][ty + i * 8];
        __nv_bfloat16 h = __float2bfloat16(v);
        Whi[ob + (size_t)n * Kd + k] = h;
        Wlo[ob + (size_t)n * Kd + k] = __float2bfloat16(v - __bfloat162float(h));
    }
}

// ---------------------------------------------------------------------
__global__ void head_kernel(const float* __restrict__ h0, const float* __restrict__ Wout,
                            const float* __restrict__ bout, float* __restrict__ out, int M)
{
    const int gw = (int)((blockIdx.x * (size_t)blockDim.x + threadIdx.x) >> 5);
    const int lane = threadIdx.x & 31;
    if (gw >= M) return;
    const float* row = h0 + (size_t)gw * HID;
    float s = 0.f;
#pragma unroll
    for (int i = 0; i < 4; i++) {
        int c = (lane + i * 32) * 4;
        float4 a = *(const float4*)(row + c);
        float4 w = *(const float4*)(Wout + c);
        s += a.x * w.x + a.y * w.y + a.z * w.z + a.w * w.w;
    }
#pragma unroll
    for (int o = 16; o; o >>= 1) s += __shfl_xor_sync(0xffffffffu, s, o);
    if (lane == 0) out[gw] = s + bout[0];
}

// ---------------------------------------------------------------------
extern "C" void kernel_launch(void* const* d_in, const int* in_sizes, int n_in,
                              void* d_out, int out_size)
{
    const float* x_all = (const float*)d_in[0];
    const float* W_in  = (const float*)d_in[1];
    const float* b_in  = (const float*)d_in[2];
    const float* W1    = (const float*)d_in[3];
    const float* b1    = (const float*)d_in[4];
    const float* W2    = (const float*)d_in[5];
    const float* b2    = (const float*)d_in[6];
    const float* W_out = (const float*)d_in[7];
    const float* b_out = (const float*)d_in[8];
    const int*   edges = (const int*)d_in[9];
    float* out = (float*)d_out;

    float *h, *h2, *y1, *y4;
    int *cnt, *off, *curp, *eidx;
    __nv_bfloat16 *Ahi, *Alo, *Mhi, *Mlo, *xhi, *xlo, *Winhi, *Winlo, *W1hi, *W1lo, *W2hi, *W2lo;
    cudaGetSymbolAddress((void**)&h,    g_h);
    cudaGetSymbolAddress((void**)&h2,   g_h2);
    cudaGetSymbolAddress((void**)&y1,   g_y1);
    cudaGetSymbolAddress((void**)&y4,   g_y4);
    cudaGetSymbolAddress((void**)&cnt,  g_cnt);
    cudaGetSymbolAddress((void**)&off,  g_off);
    cudaGetSymbolAddress((void**)&curp, g_curp);
    cudaGetSymbolAddress((void**)&eidx, g_eidx);
    cudaGetSymbolAddress((void**)&Ahi,  g_Ahi);
    cudaGetSymbolAddress((void**)&Alo,  g_Alo);
    cudaGetSymbolAddress((void**)&Mhi,  g_Mhi);
    cudaGetSymbolAddress((void**)&Mlo,  g_Mlo);
    cudaGetSymbolAddress((void**)&xhi,  g_xhi);
    cudaGetSymbolAddress((void**)&xlo,  g_xlo);
    cudaGetSymbolAddress((void**)&Winhi, g_Winhi);
    cudaGetSymbolAddress((void**)&Winlo, g_Winlo);
    cudaGetSymbolAddress((void**)&W1hi, g_W1hi);
    cudaGetSymbolAddress((void**)&W1lo, g_W1lo);
    cudaGetSymbolAddress((void**)&W2hi, g_W2hi);
    cudaGetSymbolAddress((void**)&W2lo, g_W2lo);

    cudaFuncSetAttribute(gemm_mma_b<0,512>, cudaFuncAttributeMaxDynamicSharedMemorySize, MS_TOTAL);
    cudaFuncSetAttribute(gemm_mma_b<1,512>, cudaFuncAttributeMaxDynamicSharedMemorySize, MS_TOTAL);
    cudaFuncSetAttribute(gemm_mma_b<2,64>,  cudaFuncAttributeMaxDynamicSharedMemorySize, MS_TOTAL);

    const size_t WOFF = (size_t)HID * HID;
    const int gx = (NNODES + 127) / 128;
    const int n4 = NNODES * HID / 4;
    const int nb = (n4 + 255) / 256;

    // ---- CSR build (edges fixed for the whole call) ----
    cudaMemsetAsync(cnt, 0, (size_t)NET * NNODES * sizeof(int));
    hist_kernel<<<(NET * NEDGE + 255) / 256, 256>>>(edges, cnt);
    scan_kernel<<<NET, 1024>>>(cnt, off, curp);
    fill_kernel<<<(NET * NEDGE + 255) / 256, 256>>>(edges, curp, eidx);

    // ---- weight prep + input split ----
    wconv_kernel<<<dim3(16, 16, NWMAT), dim3(32, 8)>>>(W1, W1hi, W1lo, HID, HID);
    wconv_kernel<<<dim3(16, 16, NWMAT), dim3(32, 8)>>>(W2, W2hi, W2lo, HID, HID);
    wconv_kernel<<<dim3(2, 16, NTYPES), dim3(32, 8)>>>(W_in, Winhi, Winlo, FIN, HID);
    {
        const int xn4 = NTYPES * NNODES * FIN / 4;
        split_kernel<<<(xn4 + 255) / 256, 256>>>(x_all, xhi, xlo, xn4);
    }

    // ---- input projection: all 5 types in one batched launch ----
    gemm_mma_b<2,64><<<dim3(gx, 4, NTYPES), 256, MS_TOTAL>>>(
        xhi, xlo, (size_t)NNODES * FIN, Winhi, Winlo, b_in,
        h, nullptr, nullptr, nullptr, nullptr, NNODES);

    float* cur = h;
    float* nxt = h2;
    for (int l = 0; l < 2; l++) {
        // fused GIN aggregation (CSR gather) + bf16 split, all 6 types
        gather_split_kernel<<<dim3(NNODES, NET), 128>>>(cur, off, eidx, Ahi, Alo);
        // GEMM1 for all 6 types (batched): M[t] = relu(A[t] @ W1[l,t] + b1) -> hi/lo
        gemm_mma_b<0,512><<<dim3(gx, 4, NET), 256, MS_TOTAL>>>(
            Ahi, Alo, TOFF, W1hi + (size_t)l * NET * WOFF, W1lo + (size_t)l * NET * WOFF,
            b1 + (size_t)l * NET * HID, nullptr, Mhi, Mlo, nullptr, nullptr, NNODES);
        // GEMM2 for all 6 types (batched) with dst routing
        gemm_mma_b<1,512><<<dim3(gx, 4, NET), 256, MS_TOTAL>>>(
            Mhi, Mlo, TOFF, W2hi + (size_t)l * NET * WOFF, W2lo + (size_t)l * NET * WOFF,
            b2 + (size_t)l * NET * HID, nxt, nullptr, nullptr, y1, y4, NNODES);
        // dst 0 had two writers: combine
        combine0_kernel<<<nb, 256>>>(y1, y4, nxt, n4);
        float* sw = cur; cur = nxt; nxt = sw;
    }

    // ---- output head on 'product' nodes (type 0) ----
    head_kernel<<<(NNODES * 32 + 255) / 256, 256>>>(cur, W_out, b_out, out, NNODES);
}

// round 8
// speedup vs baseline: 4.6180x; 1.8250x over previous
#include <cuda_runtime.h>
#include <cuda_bf16.h>
#include <cstdint>
#include <cstddef>

#define NNODES 20000
#define HID    512
#define NEDGE  160000
#define NTYPES 5
#define NET    6
#define FIN    64
#define NWMAT  12
#define TOFF   ((size_t)NNODES * HID)

// ---------------- scratch (__device__ globals; no allocs allowed) -------------
__device__ float g_h  [NTYPES * NNODES * HID];
__device__ float g_h2 [NTYPES * NNODES * HID];
__device__ float g_y1 [NNODES * HID];
__device__ float g_y4 [NNODES * HID];
__device__ __nv_bfloat16 g_Ahi[NET * NNODES * HID];
__device__ __nv_bfloat16 g_Alo[NET * NNODES * HID];
__device__ __nv_bfloat16 g_Mhi[NET * NNODES * HID];
__device__ __nv_bfloat16 g_Mlo[NET * NNODES * HID];
__device__ __nv_bfloat16 g_xhi[NTYPES * NNODES * FIN];
__device__ __nv_bfloat16 g_xlo[NTYPES * NNODES * FIN];
__device__ __nv_bfloat16 g_Winhi[NTYPES * HID * FIN];
__device__ __nv_bfloat16 g_Winlo[NTYPES * HID * FIN];
__device__ __nv_bfloat16 g_W1hi[NWMAT * HID * HID];
__device__ __nv_bfloat16 g_W1lo[NWMAT * HID * HID];
__device__ __nv_bfloat16 g_W2hi[NWMAT * HID * HID];
__device__ __nv_bfloat16 g_W2lo[NWMAT * HID * HID];
// CSR scratch
__device__ int g_cnt [NET * NNODES];
__device__ int g_off [NET * (NNODES + 1)];
__device__ int g_curp[NET * NNODES];
__device__ int g_eidx[NET * NEDGE];

// EDGE_TYPES = ((4,1),(1,0),(0,2),(2,3),(3,0),(1,4))
__constant__ int c_ES[NET] = {4, 1, 0, 2, 3, 1};
__constant__ int c_ED[NET] = {1, 0, 2, 3, 0, 4};
// Dead-cone-pruned active type lists:
//  [0..5]  identity (input proj etc.)
//  [6..9]  layer 0 active: {0,1,3,4}
//  [10..11] layer 1 active: {1,4}
__constant__ int c_TLA[12] = {0, 1, 2, 3, 4, 5,  0, 1, 3, 4,  1, 4};
#define TL_ID 0
#define TL_L0 6
#define TL_L1 10

// ---------------- family-common PTX helpers (sm_80+) --------------------------
__device__ __forceinline__ uint32_t smem_u32(const void* p) {
    uint32_t a;
    asm("{ .reg .u64 t; cvta.to.shared.u64 t, %1; cvt.u32.u64 %0, t; }" : "=r"(a) : "l"(p));
    return a;
}
__device__ __forceinline__ void cpasync16(uint32_t s, const void* g, int sz) {
    asm volatile("cp.async.cg.shared.global [%0], [%1], 16, %2;" :: "r"(s), "l"(g), "r"(sz));
}
__device__ __forceinline__ void cp_commit() { asm volatile("cp.async.commit_group;"); }
template<int N>
__device__ __forceinline__ void cp_wait() { asm volatile("cp.async.wait_group %0;" :: "n"(N)); }

__device__ __forceinline__ void ldsm4(uint32_t* r, uint32_t a) {
    asm volatile("ldmatrix.sync.aligned.m8n8.x4.shared.b16 {%0,%1,%2,%3}, [%4];"
                 : "=r"(r[0]), "=r"(r[1]), "=r"(r[2]), "=r"(r[3]) : "r"(a));
}
__device__ __forceinline__ void ldsm2(uint32_t* r, uint32_t a) {
    asm volatile("ldmatrix.sync.aligned.m8n8.x2.shared.b16 {%0,%1}, [%2];"
                 : "=r"(r[0]), "=r"(r[1]) : "r"(a));
}
__device__ __forceinline__ void mma16816(float* d, const uint32_t* a, const uint32_t* b) {
    asm volatile("mma.sync.aligned.m16n8k16.row.col.f32.bf16.bf16.f32 "
                 "{%0,%1,%2,%3}, {%4,%5,%6,%7}, {%8,%9}, {%0,%1,%2,%3};"
                 : "+f"(d[0]), "+f"(d[1]), "+f"(d[2]), "+f"(d[3])
                 : "r"(a[0]), "r"(a[1]), "r"(a[2]), "r"(a[3]), "r"(b[0]), "r"(b[1]));
}

// ---------------------------------------------------------------------
// Batched split-bf16 GEMM on mma.sync; t = c_TLA[tlbase + blockIdx.z].
// MODE 0: GEMM1  -> relu, bf16 hi/lo split out to Chi/Clo + t*TOFF
// MODE 1: GEMM2  -> t==1 raw->y1, t==4 raw->y4, else relu -> C + ED[t]*TOFF
// MODE 2: inproj -> relu -> C + t*TOFF
// CTA 128x128, BK=32, 8 warps, 3-stage cp.async; Ahi*Bhi + Ahi*Blo + Alo*Bhi.
// (measured at the sm_103 legacy-HMMA throughput cap: rt~16cyc/HMMA per SMSP)
// ---------------------------------------------------------------------
#define MS_A_HI 0
#define MS_A_LO 10240
#define MS_B_HI 20480
#define MS_B_LO 30720
#define MS_STAGE 40960
#define MS_TOTAL (3 * MS_STAGE)

template<int MODE, int LDK>
__global__ __launch_bounds__(256, 1)
void gemm_mma_b(const __nv_bfloat16* __restrict__ Ahi, const __nv_bfloat16* __restrict__ Alo,
                size_t aStride, int tlbase,
                const __nv_bfloat16* __restrict__ Whi, const __nv_bfloat16* __restrict__ Wlo,
                const float* __restrict__ bias,
                float* __restrict__ C,
                __nv_bfloat16* __restrict__ Chi, __nv_bfloat16* __restrict__ Clo,
                float* __restrict__ y1, float* __restrict__ y4,
                int M)
{
    constexpr int NKT = LDK / 32;
    extern __shared__ char smem[];
    const uint32_t sb = smem_u32(smem);
    const int t    = c_TLA[tlbase + blockIdx.z];
    const int tid  = threadIdx.x;
    const int lane = tid & 31;
    const int wid  = tid >> 5;
    const int wm   = (wid >> 2) * 64;
    const int wn   = (wid & 3) * 32;
    const int bm   = blockIdx.x * 128;
    const int bn   = blockIdx.y * 128;

    Ahi += (size_t)t * aStride;
    Alo += (size_t)t * aStride;
    Whi += (size_t)t * (size_t)HID * LDK;
    Wlo += (size_t)t * (size_t)HID * LDK;
    bias += (size_t)t * HID;

    auto load_stage = [&](int st, int kt) {
        const int kc = kt * 32;
        const uint32_t sbase = sb + st * MS_STAGE;
#pragma unroll
        for (int j = 0; j < 2; ++j) {
            const int c   = tid + j * 256;
            const int row = c >> 2;
            const int c16 = c & 3;
            const uint32_t so = (uint32_t)(row * 80 + c16 * 16);
            const int gr = bm + row;
            const int sz = (gr < M) ? 16 : 0;
            const size_t ga = (size_t)gr * LDK + kc + c16 * 8;
            cpasync16(sbase + MS_A_HI + so, Ahi + ga, sz);
            cpasync16(sbase + MS_A_LO + so, Alo + ga, sz);
            const size_t gb = (size_t)(bn + row) * LDK + kc + c16 * 8;
            cpasync16(sbase + MS_B_HI + so, Whi + gb, 16);
            cpasync16(sbase + MS_B_LO + so, Wlo + gb, 16);
        }
        cp_commit();
    };

    float acc[4][4][4];
#pragma unroll
    for (int mi = 0; mi < 4; ++mi)
#pragma unroll
        for (int ni = 0; ni < 4; ++ni)
#pragma unroll
            for (int q = 0; q < 4; ++q) acc[mi][ni][q] = 0.f;

    load_stage(0, 0);
    if (NKT > 1) load_stage(1, 1);

    const uint32_t a_row = (uint32_t)(lane & 15);
    const uint32_t a_k16 = (uint32_t)((lane >> 4) * 16);
    const uint32_t b_row = (uint32_t)(lane & 7);
    const uint32_t b_k16 = (uint32_t)(((lane >> 3) & 1) * 16);

#pragma unroll 1
    for (int kt = 0; kt < NKT; ++kt) {
        if (kt >= NKT - 1) cp_wait<0>();
        else               cp_wait<1>();
        __syncthreads();
        if (kt + 2 < NKT) load_stage((kt + 2) % 3, kt + 2);

        const uint32_t sbase = sb + (uint32_t)(kt % 3) * MS_STAGE;
#pragma unroll
        for (int k2 = 0; k2 < 2; ++k2) {
            const uint32_t koff = (uint32_t)(k2 * 32);
            uint32_t ah[4][4], al[4][4], bh[4][2], bl[4][2];
#pragma unroll
            for (int mi = 0; mi < 4; ++mi) {
                uint32_t ad = sbase + (uint32_t)((wm + mi * 16 + a_row) * 80) + a_k16 + koff;
                ldsm4(ah[mi], ad + MS_A_HI);
                ldsm4(al[mi], ad + MS_A_LO);
            }
#pragma unroll
            for (int ni = 0; ni < 4; ++ni) {
                uint32_t bd = sbase + (uint32_t)((wn + ni * 8 + b_row) * 80) + b_k16 + koff;
                ldsm2(bh[ni], bd + MS_B_HI);
                ldsm2(bl[ni], bd + MS_B_LO);
            }
#pragma unroll
            for (int mi = 0; mi < 4; ++mi)
#pragma unroll
                for (int ni = 0; ni < 4; ++ni) {
                    mma16816(acc[mi][ni], ah[mi], bh[ni]);
                    mma16816(acc[mi][ni], ah[mi], bl[ni]);
                    mma16816(acc[mi][ni], al[mi], bh[ni]);
                }
        }
    }

    // ---- per-mode output routing ----
    float* Cout = nullptr;
    bool doRelu = true;
    if (MODE == 0) {
        Chi += (size_t)t * TOFF;
        Clo += (size_t)t * TOFF;
    } else if (MODE == 1) {
        const int d = c_ED[t];
        if (t == 1)      { Cout = y1; doRelu = false; }
        else if (t == 4) { Cout = y4; doRelu = false; }
        else             { Cout = C + (size_t)d * TOFF; }
    } else {
        Cout = C + (size_t)t * TOFF;
    }

#pragma unroll
    for (int mi = 0; mi < 4; ++mi) {
        const int r0 = bm + wm + mi * 16 + (lane >> 2);
#pragma unroll
        for (int half = 0; half < 2; ++half) {
            const int r = r0 + half * 8;
            if (r >= M) continue;
#pragma unroll
            for (int ni = 0; ni < 4; ++ni) {
                const int c = wn + ni * 8 + (lane & 3) * 2 + bn;
                float v0 = acc[mi][ni][half * 2 + 0] + bias[c];
                float v1 = acc[mi][ni][half * 2 + 1] + bias[c + 1];
                if (MODE == 0) {
                    v0 = fmaxf(v0, 0.f); v1 = fmaxf(v1, 0.f);
                    __nv_bfloat16 h0 = __float2bfloat16(v0), h1 = __float2bfloat16(v1);
                    float l0 = v0 - __bfloat162float(h0);
                    float l1 = v1 - __bfloat162float(h1);
                    __nv_bfloat16 q0 = __float2bfloat16(l0), q1 = __float2bfloat16(l1);
                    uint32_t hp = ((uint32_t)__bfloat16_as_ushort(h1) << 16) | __bfloat16_as_ushort(h0);
                    uint32_t lp = ((uint32_t)__bfloat16_as_ushort(q1) << 16) | __bfloat16_as_ushort(q0);
                    *(uint32_t*)(Chi + (size_t)r * HID + c) = hp;
                    *(uint32_t*)(Clo + (size_t)r * HID + c) = lp;
                } else {
                    if (doRelu) { v0 = fmaxf(v0, 0.f); v1 = fmaxf(v1, 0.f); }
                    *(float2*)(Cout + (size_t)r * HID + c) = make_float2(v0, v1);
                }
            }
        }
    }
}

// ---------------------------------------------------------------------
// CSR build: histogram -> per-type exclusive scan -> fill
// ---------------------------------------------------------------------
__global__ void hist_kernel(const int* __restrict__ edges, int* __restrict__ cnt)
{
    const int i = blockIdx.x * blockDim.x + threadIdx.x;
    if (i >= NET * NEDGE) return;
    const int t = i / NEDGE, e = i - t * NEDGE;
    const int d = edges[(size_t)t * 2 * NEDGE + NEDGE + e];
    atomicAdd(&cnt[t * NNODES + d], 1);
}

__global__ void scan_kernel(const int* __restrict__ cnt, int* __restrict__ off,
                            int* __restrict__ curp)
{
    const int t = blockIdx.x;
    const int tid = threadIdx.x;
    const int lane = tid & 31, wid = tid >> 5;
    __shared__ int wsum[32];
    __shared__ int chunkTotal;
    int carry = 0;
    for (int base = 0; base < NNODES; base += 1024) {
        const int idx = base + tid;
        int v = (idx < NNODES) ? cnt[t * NNODES + idx] : 0;
        int x = v;
#pragma unroll
        for (int o = 1; o < 32; o <<= 1) {
            int y = __shfl_up_sync(0xffffffffu, x, o);
            if (lane >= o) x += y;
        }
        if (lane == 31) wsum[wid] = x;
        __syncthreads();
        if (wid == 0) {
            int w = wsum[lane];
#pragma unroll
            for (int o = 1; o < 32; o <<= 1) {
                int y = __shfl_up_sync(0xffffffffu, w, o);
                if (lane >= o) w += y;
            }
            wsum[lane] = w;
            if (lane == 31) chunkTotal = w;
        }
        __syncthreads();
        const int incl = x + (wid > 0 ? wsum[wid - 1] : 0);
        const int excl = carry + incl - v;
        if (idx < NNODES) {
            off[t * (NNODES + 1) + idx] = excl;
            curp[t * NNODES + idx] = excl;
        }
        carry += chunkTotal;
        __syncthreads();
    }
    if (tid == 0) off[t * (NNODES + 1) + NNODES] = carry;
}

__global__ void fill_kernel(const int* __restrict__ edges, int* __restrict__ curp,
                            int* __restrict__ eidx)
{
    const int i = blockIdx.x * blockDim.x + threadIdx.x;
    if (i >= NET * NEDGE) return;
    const int t = i / NEDGE, e = i - t * NEDGE;
    const int s = edges[(size_t)t * 2 * NEDGE + e];
    const int d = edges[(size_t)t * 2 * NEDGE + NEDGE + e];
    const int p = atomicAdd(&curp[t * NNODES + d], 1);
    eidx[t * NEDGE + p] = s;
}

// ---------------------------------------------------------------------
// Fused GIN aggregation via CSR gather + bf16 hi/lo split; pruned type list.
// block = (dst row, active-type z); t = c_TLA[tlbase + z].
// A[t][d] = h[ED[t]][d] + sum_{s in N_t(d)} h[ES[t]][s]   -> Ahi/Alo
// ---------------------------------------------------------------------
__global__ __launch_bounds__(128)
void gather_split_kernel(const float* __restrict__ hcur, int tlbase,
                         const int* __restrict__ off, const int* __restrict__ eidx,
                         __nv_bfloat16* __restrict__ Ahi, __nv_bfloat16* __restrict__ Alo)
{
    const int d = blockIdx.x;
    const int t = c_TLA[tlbase + blockIdx.y];
    const int c4 = threadIdx.x * 4;
    const int o0 = off[t * (NNODES + 1) + d];
    const int o1 = off[t * (NNODES + 1) + d + 1];
    const float* hsrc = hcur + (size_t)c_ES[t] * TOFF;
    const int* ei = eidx + (size_t)t * NEDGE;

    float4 acc = *(const float4*)(hcur + (size_t)c_ED[t] * TOFF + (size_t)d * HID + c4);
    for (int e = o0; e < o1; ++e) {
        const int s = __ldg(&ei[e]);
        const float4 v = *(const float4*)(hsrc + (size_t)s * HID + c4);
        acc.x += v.x; acc.y += v.y; acc.z += v.z; acc.w += v.w;
    }
    __nv_bfloat16 h0 = __float2bfloat16(acc.x), h1 = __float2bfloat16(acc.y);
    __nv_bfloat16 h2 = __float2bfloat16(acc.z), h3 = __float2bfloat16(acc.w);
    __nv_bfloat16 l0 = __float2bfloat16(acc.x - __bfloat162float(h0));
    __nv_bfloat16 l1 = __float2bfloat16(acc.y - __bfloat162float(h1));
    __nv_bfloat16 l2 = __float2bfloat16(acc.z - __bfloat162float(h2));
    __nv_bfloat16 l3 = __float2bfloat16(acc.w - __bfloat162float(h3));
    uint2 hv, lv;
    hv.x = ((uint32_t)__bfloat16_as_ushort(h1) << 16) | __bfloat16_as_ushort(h0);
    hv.y = ((uint32_t)__bfloat16_as_ushort(h3) << 16) | __bfloat16_as_ushort(h2);
    lv.x = ((uint32_t)__bfloat16_as_ushort(l1) << 16) | __bfloat16_as_ushort(l0);
    lv.y = ((uint32_t)__bfloat16_as_ushort(l3) << 16) | __bfloat16_as_ushort(l2);
    *(uint2*)(Ahi + (size_t)t * TOFF + (size_t)d * HID + c4) = hv;
    *(uint2*)(Alo + (size_t)t * TOFF + (size_t)d * HID + c4) = lv;
}

// ---------------------------------------------------------------------
__global__ void split_kernel(const float* __restrict__ a,
                             __nv_bfloat16* __restrict__ hi, __nv_bfloat16* __restrict__ lo,
                             int n4)
{
    int i = blockIdx.x * blockDim.x + threadIdx.x;
    if (i >= n4) return;
    float4 va = ((const float4*)a)[i];
    __nv_bfloat16 h0 = __float2bfloat16(va.x), h1 = __float2bfloat16(va.y);
    __nv_bfloat16 h2 = __float2bfloat16(va.z), h3 = __float2bfloat16(va.w);
    __nv_bfloat16 l0 = __float2bfloat16(va.x - __bfloat162float(h0));
    __nv_bfloat16 l1 = __float2bfloat16(va.y - __bfloat162float(h1));
    __nv_bfloat16 l2 = __float2bfloat16(va.z - __bfloat162float(h2));
    __nv_bfloat16 l3 = __float2bfloat16(va.w - __bfloat162float(h3));
    uint2 hv, lv;
    hv.x = ((uint32_t)__bfloat16_as_ushort(h1) << 16) | __bfloat16_as_ushort(h0);
    hv.y = ((uint32_t)__bfloat16_as_ushort(h3) << 16) | __bfloat16_as_ushort(h2);
    lv.x = ((uint32_t)__bfloat16_as_ushort(l1) << 16) | __bfloat16_as_ushort(l0);
    lv.y = ((uint32_t)__bfloat16_as_ushort(l3) << 16) | __bfloat16_as_ushort(l2);
    ((uint2*)hi)[i] = hv;
    ((uint2*)lo)[i] = lv;
}

// combine dst-0 (layer 0): out = relu(y1 + y4)
__global__ void combine0_kernel(const float* __restrict__ y1, const float* __restrict__ y4,
                                float* __restrict__ o, int n4)
{
    int i = blockIdx.x * blockDim.x + threadIdx.x;
    if (i >= n4) return;
    float4 a = ((const float4*)y1)[i];
    float4 b = ((const float4*)y4)[i];
    float4 v;
    v.x = fmaxf(a.x + b.x, 0.f);
    v.y = fmaxf(a.y + b.y, 0.f);
    v.z = fmaxf(a.z + b.z, 0.f);
    v.w = fmaxf(a.w + b.w, 0.f);
    ((float4*)o)[i] = v;
}

// transpose + split weights: W[m][Kd][Nd] fp32 -> Wt_hi/lo[m][Nd][Kd] bf16
__global__ void wconv_kernel(const float* __restrict__ W,
                             __nv_bfloat16* __restrict__ Whi, __nv_bfloat16* __restrict__ Wlo,
                             int Kd, int Nd)
{
    __shared__ float t[32][33];
    const int m = blockIdx.z;
    const int k0 = blockIdx.x * 32, n0 = blockIdx.y * 32;
    const int tx = threadIdx.x, ty = threadIdx.y;
    const float* Wm = W + (size_t)m * Kd * Nd;
#pragma unroll
    for (int i = 0; i < 4; i++)
        t[ty + i * 8][tx] = Wm[(size_t)(k0 + ty + i * 8) * Nd + n0 + tx];
    __syncthreads();
    const size_t ob = (size_t)m * Kd * Nd;
#pragma unroll
    for (int i = 0; i < 4; i++) {
        int n = n0 + ty + i * 8, k = k0 + tx;
        float v = t[tx][ty + i * 8];
        __nv_bfloat16 h = __float2bfloat16(v);
        Whi[ob + (size_t)n * Kd + k] = h;
        Wlo[ob + (size_t)n * Kd + k] = __float2bfloat16(v - __bfloat162float(h));
    }
}

// ---------------------------------------------------------------------
// Fused final: out[i] = dot(relu(y1[i]+y4[i]), Wout) + bout  (one warp/row)
// ---------------------------------------------------------------------
__global__ void head2_kernel(const float* __restrict__ y1, const float* __restrict__ y4,
                             const float* __restrict__ Wout, const float* __restrict__ bout,
                             float* __restrict__ out, int M)
{
    const int gw = (int)((blockIdx.x * (size_t)blockDim.x + threadIdx.x) >> 5);
    const int lane = threadIdx.x & 31;
    if (gw >= M) return;
    const float* r1 = y1 + (size_t)gw * HID;
    const float* r4 = y4 + (size_t)gw * HID;
    float s = 0.f;
#pragma unroll
    for (int i = 0; i < 4; i++) {
        int c = (lane + i * 32) * 4;
        float4 a = *(const float4*)(r1 + c);
        float4 b = *(const float4*)(r4 + c);
        float4 w = *(const float4*)(Wout + c);
        s += fmaxf(a.x + b.x, 0.f) * w.x + fmaxf(a.y + b.y, 0.f) * w.y
           + fmaxf(a.z + b.z, 0.f) * w.z + fmaxf(a.w + b.w, 0.f) * w.w;
    }
#pragma unroll
    for (int o = 16; o; o >>= 1) s += __shfl_xor_sync(0xffffffffu, s, o);
    if (lane == 0) out[gw] = s + bout[0];
}

// ---------------------------------------------------------------------
extern "C" void kernel_launch(void* const* d_in, const int* in_sizes, int n_in,
                              void* d_out, int out_size)
{
    const float* x_all = (const float*)d_in[0];
    const float* W_in  = (const float*)d_in[1];
    const float* b_in  = (const float*)d_in[2];
    const float* W1    = (const float*)d_in[3];
    const float* b1    = (const float*)d_in[4];
    const float* W2    = (const float*)d_in[5];
    const float* b2    = (const float*)d_in[6];
    const float* W_out = (const float*)d_in[7];
    const float* b_out = (const float*)d_in[8];
    const int*   edges = (const int*)d_in[9];
    float* out = (float*)d_out;

    float *h, *h2, *y1, *y4;
    int *cnt, *off, *curp, *eidx;
    __nv_bfloat16 *Ahi, *Alo, *Mhi, *Mlo, *xhi, *xlo, *Winhi, *Winlo, *W1hi, *W1lo, *W2hi, *W2lo;
    cudaGetSymbolAddress((void**)&h,    g_h);
    cudaGetSymbolAddress((void**)&h2,   g_h2);
    cudaGetSymbolAddress((void**)&y1,   g_y1);
    cudaGetSymbolAddress((void**)&y4,   g_y4);
    cudaGetSymbolAddress((void**)&cnt,  g_cnt);
    cudaGetSymbolAddress((void**)&off,  g_off);
    cudaGetSymbolAddress((void**)&curp, g_curp);
    cudaGetSymbolAddress((void**)&eidx, g_eidx);
    cudaGetSymbolAddress((void**)&Ahi,  g_Ahi);
    cudaGetSymbolAddress((void**)&Alo,  g_Alo);
    cudaGetSymbolAddress((void**)&Mhi,  g_Mhi);
    cudaGetSymbolAddress((void**)&Mlo,  g_Mlo);
    cudaGetSymbolAddress((void**)&xhi,  g_xhi);
    cudaGetSymbolAddress((void**)&xlo,  g_xlo);
    cudaGetSymbolAddress((void**)&Winhi, g_Winhi);
    cudaGetSymbolAddress((void**)&Winlo, g_Winlo);
    cudaGetSymbolAddress((void**)&W1hi, g_W1hi);
    cudaGetSymbolAddress((void**)&W1lo, g_W1lo);
    cudaGetSymbolAddress((void**)&W2hi, g_W2hi);
    cudaGetSymbolAddress((void**)&W2lo, g_W2lo);

    cudaFuncSetAttribute(gemm_mma_b<0,512>, cudaFuncAttributeMaxDynamicSharedMemorySize, MS_TOTAL);
    cudaFuncSetAttribute(gemm_mma_b<1,512>, cudaFuncAttributeMaxDynamicSharedMemorySize, MS_TOTAL);
    cudaFuncSetAttribute(gemm_mma_b<2,64>,  cudaFuncAttributeMaxDynamicSharedMemorySize, MS_TOTAL);

    const size_t WOFF = (size_t)HID * HID;
    const int gx = (NNODES + 127) / 128;
    const int n4 = NNODES * HID / 4;
    const int nb = (n4 + 255) / 256;

    // ---- CSR build (edges fixed for the whole call) ----
    cudaMemsetAsync(cnt, 0, (size_t)NET * NNODES * sizeof(int));
    hist_kernel<<<(NET * NEDGE + 255) / 256, 256>>>(edges, cnt);
    scan_kernel<<<NET, 1024>>>(cnt, off, curp);
    fill_kernel<<<(NET * NEDGE + 255) / 256, 256>>>(edges, curp, eidx);

    // ---- weight prep + input split ----
    wconv_kernel<<<dim3(16, 16, NWMAT), dim3(32, 8)>>>(W1, W1hi, W1lo, HID, HID);
    wconv_kernel<<<dim3(16, 16, NWMAT), dim3(32, 8)>>>(W2, W2hi, W2lo, HID, HID);
    wconv_kernel<<<dim3(2, 16, NTYPES), dim3(32, 8)>>>(W_in, Winhi, Winlo, FIN, HID);
    {
        const int xn4 = NTYPES * NNODES * FIN / 4;
        split_kernel<<<(xn4 + 255) / 256, 256>>>(x_all, xhi, xlo, xn4);
    }

    // ---- input projection: all 5 types in one batched launch ----
    gemm_mma_b<2,64><<<dim3(gx, 4, NTYPES), 256, MS_TOTAL>>>(
        xhi, xlo, (size_t)NNODES * FIN, TL_ID, Winhi, Winlo, b_in,
        h, nullptr, nullptr, nullptr, nullptr, NNODES);

    // ================= layer 0: active t = {0,1,3,4} =================
    gather_split_kernel<<<dim3(NNODES, 4), 128>>>(h, TL_L0, off, eidx, Ahi, Alo);
    gemm_mma_b<0,512><<<dim3(gx, 4, 4), 256, MS_TOTAL>>>(
        Ahi, Alo, TOFF, TL_L0, W1hi, W1lo, b1,
        nullptr, Mhi, Mlo, nullptr, nullptr, NNODES);
    gemm_mma_b<1,512><<<dim3(gx, 4, 4), 256, MS_TOTAL>>>(
        Mhi, Mlo, TOFF, TL_L0, W2hi, W2lo, b2,
        h2, nullptr, nullptr, y1, y4, NNODES);
    combine0_kernel<<<nb, 256>>>(y1, y4, h2, n4);   // h2[0] = relu(y1+y4)

    // ================= layer 1: active t = {1,4} =====================
    gather_split_kernel<<<dim3(NNODES, 2), 128>>>(h2, TL_L1, off, eidx, Ahi, Alo);
    gemm_mma_b<0,512><<<dim3(gx, 4, 2), 256, MS_TOTAL>>>(
        Ahi, Alo, TOFF, TL_L1, W1hi + (size_t)NET * WOFF, W1lo + (size_t)NET * WOFF,
        b1 + (size_t)NET * HID, nullptr, Mhi, Mlo, nullptr, nullptr, NNODES);
    gemm_mma_b<1,512><<<dim3(gx, 4, 2), 256, MS_TOTAL>>>(
        Mhi, Mlo, TOFF, TL_L1, W2hi + (size_t)NET * WOFF, W2lo + (size_t)NET * WOFF,
        b2 + (size_t)NET * HID, nullptr, nullptr, nullptr, y1, y4, NNODES);

    // ---- fused combine + output head on 'product' nodes ----
    head2_kernel<<<(NNODES * 32 + 255) / 256, 256>>>(y1, y4, W_out, b_out, out, NNODES);
}

// round 10
// speedup vs baseline: 4.6337x; 1.0034x over previous
#include <cuda_runtime.h>
#include <cuda_bf16.h>
#include <cstdint>
#include <cstddef>

#define NNODES 20000
#define HID    512
#define NEDGE  160000
#define NTYPES 5
#define NET    6
#define FIN    64
#define NWMAT  12
#define TOFF   ((size_t)NNODES * HID)

// ---------------- scratch (__device__ globals; no allocs allowed) -------------
__device__ float g_h  [NTYPES * NNODES * HID];
__device__ float g_h2 [NTYPES * NNODES * HID];
__device__ float g_y1 [NNODES * HID];
__device__ float g_y4 [NNODES * HID];
__device__ __nv_bfloat16 g_Ahi[NET * NNODES * HID];
__device__ __nv_bfloat16 g_Alo[NET * NNODES * HID];
__device__ __nv_bfloat16 g_Mhi[NET * NNODES * HID];
__device__ __nv_bfloat16 g_Mlo[NET * NNODES * HID];
__device__ __nv_bfloat16 g_xhi[NTYPES * NNODES * FIN];
__device__ __nv_bfloat16 g_xlo[NTYPES * NNODES * FIN];
__device__ __nv_bfloat16 g_Winhi[NTYPES * HID * FIN];
__device__ __nv_bfloat16 g_Winlo[NTYPES * HID * FIN];
__device__ __nv_bfloat16 g_W1hi[NWMAT * HID * HID];
__device__ __nv_bfloat16 g_W1lo[NWMAT * HID * HID];
__device__ __nv_bfloat16 g_W2hi[NWMAT * HID * HID];
__device__ __nv_bfloat16 g_W2lo[NWMAT * HID * HID];
// CSR scratch
__device__ int g_cnt [NET * NNODES];
__device__ int g_off [NET * (NNODES + 1)];
__device__ int g_curp[NET * NNODES];
__device__ int g_eidx[NET * NEDGE];

// EDGE_TYPES = ((4,1),(1,0),(0,2),(2,3),(3,0),(1,4))
__constant__ int c_ES[NET] = {4, 1, 0, 2, 3, 1};
__constant__ int c_ED[NET] = {1, 0, 2, 3, 0, 4};
// Dead-cone-pruned active type lists:
//  [0..5] identity; [6..9] layer 0: {0,1,3,4}; [10..11] layer 1: {1,4}
__constant__ int c_TLA[12] = {0, 1, 2, 3, 4, 5,  0, 1, 3, 4,  1, 4};
#define TL_ID 0
#define TL_L0 6
#define TL_L1 10
__constant__ int c_WMAP[6] = {0, 1, 3, 4, 7, 10};   // live (l*NET+t) weight mats
__constant__ int c_CSRT[4] = {0, 1, 3, 4};          // edge types ever gathered

// ---------------- family-common PTX helpers (sm_80+) --------------------------
__device__ __forceinline__ uint32_t smem_u32(const void* p) {
    uint32_t a;
    asm("{ .reg .u64 t; cvta.to.shared.u64 t, %1; cvt.u32.u64 %0, t; }" : "=r"(a) : "l"(p));
    return a;
}
__device__ __forceinline__ void cpasync16(uint32_t s, const void* g, int sz) {
    asm volatile("cp.async.cg.shared.global [%0], [%1], 16, %2;" :: "r"(s), "l"(g), "r"(sz));
}
__device__ __forceinline__ void cp_commit() { asm volatile("cp.async.commit_group;"); }
template<int N>
__device__ __forceinline__ void cp_wait() { asm volatile("cp.async.wait_group %0;" :: "n"(N)); }

__device__ __forceinline__ void ldsm4(uint32_t* r, uint32_t a) {
    asm volatile("ldmatrix.sync.aligned.m8n8.x4.shared.b16 {%0,%1,%2,%3}, [%4];"
                 : "=r"(r[0]), "=r"(r[1]), "=r"(r[2]), "=r"(r[3]) : "r"(a));
}
__device__ __forceinline__ void ldsm2(uint32_t* r, uint32_t a) {
    asm volatile("ldmatrix.sync.aligned.m8n8.x2.shared.b16 {%0,%1}, [%2];"
                 : "=r"(r[0]), "=r"(r[1]) : "r"(a));
}
__device__ __forceinline__ void mma16816(float* d, const uint32_t* a, const uint32_t* b) {
    asm volatile("mma.sync.aligned.m16n8k16.row.col.f32.bf16.bf16.f32 "
                 "{%0,%1,%2,%3}, {%4,%5,%6,%7}, {%8,%9}, {%0,%1,%2,%3};"
                 : "+f"(d[0]), "+f"(d[1]), "+f"(d[2]), "+f"(d[3])
                 : "r"(a[0]), "r"(a[1]), "r"(a[2]), "r"(a[3]), "r"(b[0]), "r"(b[1]));
}
__device__ __forceinline__ void bf16_split2(float v0, float v1, uint32_t& hp, uint32_t& lp) {
    __nv_bfloat16 h0 = __float2bfloat16(v0), h1 = __float2bfloat16(v1);
    float l0 = v0 - __bfloat162float(h0);
    float l1 = v1 - __bfloat162float(h1);
    __nv_bfloat16 q0 = __float2bfloat16(l0), q1 = __float2bfloat16(l1);
    hp = ((uint32_t)__bfloat16_as_ushort(h1) << 16) | __bfloat16_as_ushort(h0);
    lp = ((uint32_t)__bfloat16_as_ushort(q1) << 16) | __bfloat16_as_ushort(q0);
}

// ---------------------------------------------------------------------
// Batched 3-product split-bf16 GEMM on mma.sync; t = c_TLA[tlbase + blockIdx.z].
// MODE 0: GEMM1  -> relu, bf16 hi/lo out to Chi/Clo + t*TOFF
// MODE 1: GEMM2  -> t==1 raw->y1, t==4 raw->y4, else relu -> C + ED[t]*TOFF
// MODE 2: inproj -> relu -> fp32 C + t*TOFF
// CTA 128x128, BK=32, 8 warps, 3-stage cp.async; Ahi*Bhi + Ahi*Blo + Alo*Bhi.
// (measured at the sm_103 legacy-HMMA throughput cap: rt~16cyc/HMMA per SMSP)
// ---------------------------------------------------------------------
#define MS_A_HI 0
#define MS_A_LO 10240
#define MS_B_HI 20480
#define MS_B_LO 30720
#define MS_STAGE 40960
#define MS_TOTAL (3 * MS_STAGE)

template<int MODE, int LDK>
__global__ __launch_bounds__(256, 1)
void gemm_mma_b(const __nv_bfloat16* __restrict__ Ahi, const __nv_bfloat16* __restrict__ Alo,
                size_t aStride, int tlbase,
                const __nv_bfloat16* __restrict__ Whi, const __nv_bfloat16* __restrict__ Wlo,
                const float* __restrict__ bias,
                float* __restrict__ C,
                __nv_bfloat16* __restrict__ Chi, __nv_bfloat16* __restrict__ Clo,
                float* __restrict__ y1, float* __restrict__ y4,
                int M)
{
    constexpr int NKT = LDK / 32;
    extern __shared__ char smem[];
    const uint32_t sb = smem_u32(smem);
    const int t    = c_TLA[tlbase + blockIdx.z];
    const int tid  = threadIdx.x;
    const int lane = tid & 31;
    const int wid  = tid >> 5;
    const int wm   = (wid >> 2) * 64;
    const int wn   = (wid & 3) * 32;
    const int bm   = blockIdx.x * 128;
    const int bn   = blockIdx.y * 128;

    Ahi += (size_t)t * aStride;
    Alo += (size_t)t * aStride;
    Whi += (size_t)t * (size_t)HID * LDK;
    Wlo += (size_t)t * (size_t)HID * LDK;
    bias += (size_t)t * HID;

    auto load_stage = [&](int st, int kt) {
        const int kc = kt * 32;
        const uint32_t sbase = sb + st * MS_STAGE;
#pragma unroll
        for (int j = 0; j < 2; ++j) {
            const int c   = tid + j * 256;
            const int row = c >> 2;
            const int c16 = c & 3;
            const uint32_t so = (uint32_t)(row * 80 + c16 * 16);
            const int gr = bm + row;
            const int sz = (gr < M) ? 16 : 0;
            const size_t ga = (size_t)gr * LDK + kc + c16 * 8;
            cpasync16(sbase + MS_A_HI + so, Ahi + ga, sz);
            cpasync16(sbase + MS_A_LO + so, Alo + ga, sz);
            const size_t gb = (size_t)(bn + row) * LDK + kc + c16 * 8;
            cpasync16(sbase + MS_B_HI + so, Whi + gb, 16);
            cpasync16(sbase + MS_B_LO + so, Wlo + gb, 16);
        }
        cp_commit();
    };

    float acc[4][4][4];
#pragma unroll
    for (int mi = 0; mi < 4; ++mi)
#pragma unroll
        for (int ni = 0; ni < 4; ++ni)
#pragma unroll
            for (int q = 0; q < 4; ++q) acc[mi][ni][q] = 0.f;

    load_stage(0, 0);
    if (NKT > 1) load_stage(1, 1);

    const uint32_t a_row = (uint32_t)(lane & 15);
    const uint32_t a_k16 = (uint32_t)((lane >> 4) * 16);
    const uint32_t b_row = (uint32_t)(lane & 7);
    const uint32_t b_k16 = (uint32_t)(((lane >> 3) & 1) * 16);

#pragma unroll 1
    for (int kt = 0; kt < NKT; ++kt) {
        if (kt >= NKT - 1) cp_wait<0>();
        else               cp_wait<1>();
        __syncthreads();
        if (kt + 2 < NKT) load_stage((kt + 2) % 3, kt + 2);

        const uint32_t sbase = sb + (uint32_t)(kt % 3) * MS_STAGE;
#pragma unroll
        for (int k2 = 0; k2 < 2; ++k2) {
            const uint32_t koff = (uint32_t)(k2 * 32);
            uint32_t ah[4][4], al[4][4], bh[4][2], bl[4][2];
#pragma unroll
            for (int mi = 0; mi < 4; ++mi) {
                uint32_t ad = sbase + (uint32_t)((wm + mi * 16 + a_row) * 80) + a_k16 + koff;
                ldsm4(ah[mi], ad + MS_A_HI);
                ldsm4(al[mi], ad + MS_A_LO);
            }
#pragma unroll
            for (int ni = 0; ni < 4; ++ni) {
                uint32_t bd = sbase + (uint32_t)((wn + ni * 8 + b_row) * 80) + b_k16 + koff;
                ldsm2(bh[ni], bd + MS_B_HI);
                ldsm2(bl[ni], bd + MS_B_LO);
            }
#pragma unroll
            for (int mi = 0; mi < 4; ++mi)
#pragma unroll
                for (int ni = 0; ni < 4; ++ni) {
                    mma16816(acc[mi][ni], ah[mi], bh[ni]);
                    mma16816(acc[mi][ni], ah[mi], bl[ni]);
                    mma16816(acc[mi][ni], al[mi], bh[ni]);
                }
        }
    }

    // ---- per-mode output routing ----
    float* Cout = nullptr;
    bool doRelu = true;
    if (MODE == 0) {
        Chi += (size_t)t * TOFF;
        Clo += (size_t)t * TOFF;
    } else if (MODE == 1) {
        const int d = c_ED[t];
        if (t == 1)      { Cout = y1; doRelu = false; }
        else if (t == 4) { Cout = y4; doRelu = false; }
        else             { Cout = C + (size_t)d * TOFF; }
    } else {
        Cout = C + (size_t)t * TOFF;
    }

#pragma unroll
    for (int mi = 0; mi < 4; ++mi) {
        const int r0 = bm + wm + mi * 16 + (lane >> 2);
#pragma unroll
        for (int half = 0; half < 2; ++half) {
            const int r = r0 + half * 8;
            if (r >= M) continue;
#pragma unroll
            for (int ni = 0; ni < 4; ++ni) {
                const int c = wn + ni * 8 + (lane & 3) * 2 + bn;
                float v0 = acc[mi][ni][half * 2 + 0] + bias[c];
                float v1 = acc[mi][ni][half * 2 + 1] + bias[c + 1];
                if (MODE == 0) {
                    v0 = fmaxf(v0, 0.f); v1 = fmaxf(v1, 0.f);
                    uint32_t hp, lp;
                    bf16_split2(v0, v1, hp, lp);
                    *(uint32_t*)(Chi + (size_t)r * HID + c) = hp;
                    *(uint32_t*)(Clo + (size_t)r * HID + c) = lp;
                } else {
                    if (doRelu) { v0 = fmaxf(v0, 0.f); v1 = fmaxf(v1, 0.f); }
                    *(float2*)(Cout + (size_t)r * HID + c) = make_float2(v0, v1);
                }
            }
        }
    }
}

// ---------------------------------------------------------------------
// CSR build for ACTIVE edge types only: histogram -> scan -> fill
// ---------------------------------------------------------------------
__global__ void hist_kernel(const int* __restrict__ edges, int* __restrict__ cnt)
{
    const int i = blockIdx.x * blockDim.x + threadIdx.x;
    if (i >= 4 * NEDGE) return;
    const int t = c_CSRT[i / NEDGE], e = i % NEDGE;
    const int d = edges[(size_t)t * 2 * NEDGE + NEDGE + e];
    atomicAdd(&cnt[t * NNODES + d], 1);
}

__global__ void scan_kernel(const int* __restrict__ cnt, int* __restrict__ off,
                            int* __restrict__ curp)
{
    const int t = c_CSRT[blockIdx.x];
    const int tid = threadIdx.x;
    const int lane = tid & 31, wid = tid >> 5;
    __shared__ int wsum[32];
    __shared__ int chunkTotal;
    int carry = 0;
    for (int base = 0; base < NNODES; base += 1024) {
        const int idx = base + tid;
        int v = (idx < NNODES) ? cnt[t * NNODES + idx] : 0;
        int x = v;
#pragma unroll
        for (int o = 1; o < 32; o <<= 1) {
            int y = __shfl_up_sync(0xffffffffu, x, o);
            if (lane >= o) x += y;
        }
        if (lane == 31) wsum[wid] = x;
        __syncthreads();
        if (wid == 0) {
            int w = wsum[lane];
#pragma unroll
            for (int o = 1; o < 32; o <<= 1) {
                int y = __shfl_up_sync(0xffffffffu, w, o);
                if (lane >= o) w += y;
            }
            wsum[lane] = w;
            if (lane == 31) chunkTotal = w;
        }
        __syncthreads();
        const int incl = x + (wid > 0 ? wsum[wid - 1] : 0);
        const int excl = carry + incl - v;
        if (idx < NNODES) {
            off[t * (NNODES + 1) + idx] = excl;
            curp[t * NNODES + idx] = excl;
        }
        carry += chunkTotal;
        __syncthreads();
    }
    if (tid == 0) off[t * (NNODES + 1) + NNODES] = carry;
}

__global__ void fill_kernel(const int* __restrict__ edges, int* __restrict__ curp,
                            int* __restrict__ eidx)
{
    const int i = blockIdx.x * blockDim.x + threadIdx.x;
    if (i >= 4 * NEDGE) return;
    const int t = c_CSRT[i / NEDGE], e = i % NEDGE;
    const int s = edges[(size_t)t * 2 * NEDGE + e];
    const int d = edges[(size_t)t * 2 * NEDGE + NEDGE + e];
    const int p = atomicAdd(&curp[t * NNODES + d], 1);
    eidx[t * NEDGE + p] = s;
}

// ---------------------------------------------------------------------
// Fused GIN aggregation via CSR gather + bf16 hi/lo split; pruned type list.
// block = (dst row, active-type z); t = c_TLA[tlbase + z].
// A[t][d] = selfterm + sum_{s in N_t(d)} hsrc[s]  -> Ahi/Alo
// Layer 1 (useY): dst type is 0 and h2[0] is never materialized — the self
// term is computed inline as relu(y1[d] + y4[d]).
// ---------------------------------------------------------------------
__global__ __launch_bounds__(128)
void gather_split_kernel(const float* __restrict__ hcur, int tlbase, int useY,
                         const float* __restrict__ y1, const float* __restrict__ y4,
                         const int* __restrict__ off, const int* __restrict__ eidx,
                         __nv_bfloat16* __restrict__ Ahi, __nv_bfloat16* __restrict__ Alo)
{
    const int d = blockIdx.x;
    const int t = c_TLA[tlbase + blockIdx.y];
    const int c4 = threadIdx.x * 4;
    const int o0 = off[t * (NNODES + 1) + d];
    const int o1 = off[t * (NNODES + 1) + d + 1];
    const float* hsrc = hcur + (size_t)c_ES[t] * TOFF;
    const int* ei = eidx + (size_t)t * NEDGE;

    float4 acc;
    if (useY) {   // layer-1 dst is type 0: self term = relu(y1 + y4)
        const float4 a = *(const float4*)(y1 + (size_t)d * HID + c4);
        const float4 b = *(const float4*)(y4 + (size_t)d * HID + c4);
        acc.x = fmaxf(a.x + b.x, 0.f);
        acc.y = fmaxf(a.y + b.y, 0.f);
        acc.z = fmaxf(a.z + b.z, 0.f);
        acc.w = fmaxf(a.w + b.w, 0.f);
    } else {
        acc = *(const float4*)(hcur + (size_t)c_ED[t] * TOFF + (size_t)d * HID + c4);
    }
    for (int e = o0; e < o1; ++e) {
        const int s = __ldg(&ei[e]);
        const float4 v = *(const float4*)(hsrc + (size_t)s * HID + c4);
        acc.x += v.x; acc.y += v.y; acc.z += v.z; acc.w += v.w;
    }
    uint2 hv, lv;
    bf16_split2(acc.x, acc.y, hv.x, lv.x);
    bf16_split2(acc.z, acc.w, hv.y, lv.y);
    *(uint2*)(Ahi + (size_t)t * TOFF + (size_t)d * HID + c4) = hv;
    *(uint2*)(Alo + (size_t)t * TOFF + (size_t)d * HID + c4) = lv;
}

// ---------------------------------------------------------------------
__global__ void split_kernel(const float* __restrict__ a,
                             __nv_bfloat16* __restrict__ hi, __nv_bfloat16* __restrict__ lo,
                             int n4)
{
    int i = blockIdx.x * blockDim.x + threadIdx.x;
    if (i >= n4) return;
    float4 v = ((const float4*)a)[i];
    uint2 hv, lv;
    bf16_split2(v.x, v.y, hv.x, lv.x);
    bf16_split2(v.z, v.w, hv.y, lv.y);
    ((uint2*)hi)[i] = hv;
    ((uint2*)lo)[i] = lv;
}

// transpose + bf16 split: W[m][Kd][Nd] fp32 -> Wt_hi/lo[m][Nd][Kd]
// useMap: m = c_WMAP[blockIdx.z] (live W1/W2 mats), else m = blockIdx.z
__global__ void wconv_kernel(const float* __restrict__ W,
                             __nv_bfloat16* __restrict__ Whi, __nv_bfloat16* __restrict__ Wlo,
                             int Kd, int Nd, int useMap)
{
    __shared__ float t[32][33];
    const int m = useMap ? c_WMAP[blockIdx.z] : blockIdx.z;
    const int k0 = blockIdx.x * 32, n0 = blockIdx.y * 32;
    const int tx = threadIdx.x, ty = threadIdx.y;
    const float* Wm = W + (size_t)m * Kd * Nd;
#pragma unroll
    for (int i = 0; i < 4; i++)
        t[ty + i * 8][tx] = Wm[(size_t)(k0 + ty + i * 8) * Nd + n0 + tx];
    __syncthreads();
    const size_t ob = (size_t)m * Kd * Nd;
#pragma unroll
    for (int i = 0; i < 4; i++) {
        int n = n0 + ty + i * 8, k = k0 + tx;
        float v = t[tx][ty + i * 8];
        __nv_bfloat16 h = __float2bfloat16(v);
        Whi[ob + (size_t)n * Kd + k] = h;
        Wlo[ob + (size_t)n * Kd + k] = __float2bfloat16(v - __bfloat162float(h));
    }
}

// ---------------------------------------------------------------------
// Fused final: out[i] = dot(relu(y1[i]+y4[i]), Wout) + bout  (one warp/row)
// ---------------------------------------------------------------------
__global__ void head2_kernel(const float* __restrict__ y1, const float* __restrict__ y4,
                             const float* __restrict__ Wout, const float* __restrict__ bout,
                             float* __restrict__ out, int M)
{
    const int gw = (int)((blockIdx.x * (size_t)blockDim.x + threadIdx.x) >> 5);
    const int lane = threadIdx.x & 31;
    if (gw >= M) return;
    const float* r1 = y1 + (size_t)gw * HID;
    const float* r4 = y4 + (size_t)gw * HID;
    float s = 0.f;
#pragma unroll
    for (int i = 0; i < 4; i++) {
        int c = (lane + i * 32) * 4;
        float4 a = *(const float4*)(r1 + c);
        float4 b = *(const float4*)(r4 + c);
        float4 w = *(const float4*)(Wout + c);
        s += fmaxf(a.x + b.x, 0.f) * w.x + fmaxf(a.y + b.y, 0.f) * w.y
           + fmaxf(a.z + b.z, 0.f) * w.z + fmaxf(a.w + b.w, 0.f) * w.w;
    }
#pragma unroll
    for (int o = 16; o; o >>= 1) s += __shfl_xor_sync(0xffffffffu, s, o);
    if (lane == 0) out[gw] = s + bout[0];
}

// ---------------------------------------------------------------------
extern "C" void kernel_launch(void* const* d_in, const int* in_sizes, int n_in,
                              void* d_out, int out_size)
{
    const float* x_all = (const float*)d_in[0];
    const float* W_in  = (const float*)d_in[1];
    const float* b_in  = (const float*)d_in[2];
    const float* W1    = (const float*)d_in[3];
    const float* b1    = (const float*)d_in[4];
    const float* W2    = (const float*)d_in[5];
    const float* b2    = (const float*)d_in[6];
    const float* W_out = (const float*)d_in[7];
    const float* b_out = (const float*)d_in[8];
    const int*   edges = (const int*)d_in[9];
    float* out = (float*)d_out;

    float *h, *h2, *y1, *y4;
    int *cnt, *off, *curp, *eidx;
    __nv_bfloat16 *Ahi, *Alo, *Mhi, *Mlo, *xhi, *xlo, *Winhi, *Winlo, *W1hi, *W1lo, *W2hi, *W2lo;
    cudaGetSymbolAddress((void**)&h,    g_h);
    cudaGetSymbolAddress((void**)&h2,   g_h2);
    cudaGetSymbolAddress((void**)&y1,   g_y1);
    cudaGetSymbolAddress((void**)&y4,   g_y4);
    cudaGetSymbolAddress((void**)&cnt,  g_cnt);
    cudaGetSymbolAddress((void**)&off,  g_off);
    cudaGetSymbolAddress((void**)&curp, g_curp);
    cudaGetSymbolAddress((void**)&eidx, g_eidx);
    cudaGetSymbolAddress((void**)&Ahi,  g_Ahi);
    cudaGetSymbolAddress((void**)&Alo,  g_Alo);
    cudaGetSymbolAddress((void**)&Mhi,  g_Mhi);
    cudaGetSymbolAddress((void**)&Mlo,  g_Mlo);
    cudaGetSymbolAddress((void**)&xhi,  g_xhi);
    cudaGetSymbolAddress((void**)&xlo,  g_xlo);
    cudaGetSymbolAddress((void**)&Winhi, g_Winhi);
    cudaGetSymbolAddress((void**)&Winlo, g_Winlo);
    cudaGetSymbolAddress((void**)&W1hi, g_W1hi);
    cudaGetSymbolAddress((void**)&W1lo, g_W1lo);
    cudaGetSymbolAddress((void**)&W2hi, g_W2hi);
    cudaGetSymbolAddress((void**)&W2lo, g_W2lo);

    cudaFuncSetAttribute(gemm_mma_b<0,512>, cudaFuncAttributeMaxDynamicSharedMemorySize, MS_TOTAL);
    cudaFuncSetAttribute(gemm_mma_b<1,512>, cudaFuncAttributeMaxDynamicSharedMemorySize, MS_TOTAL);
    cudaFuncSetAttribute(gemm_mma_b<2,64>,  cudaFuncAttributeMaxDynamicSharedMemorySize, MS_TOTAL);

    const size_t WOFF = (size_t)HID * HID;
    const int gx = (NNODES + 127) / 128;

    // ---- CSR build (active edge types only) ----
    cudaMemsetAsync(cnt, 0, (size_t)NET * NNODES * sizeof(int));
    hist_kernel<<<(4 * NEDGE + 255) / 256, 256>>>(edges, cnt);
    scan_kernel<<<4, 1024>>>(cnt, off, curp);
    fill_kernel<<<(4 * NEDGE + 255) / 256, 256>>>(edges, curp, eidx);

    // ---- weight prep (live mats only) + input split ----
    wconv_kernel<<<dim3(16, 16, 6), dim3(32, 8)>>>(W1, W1hi, W1lo, HID, HID, 1);
    wconv_kernel<<<dim3(16, 16, 6), dim3(32, 8)>>>(W2, W2hi, W2lo, HID, HID, 1);
    wconv_kernel<<<dim3(2, 16, NTYPES), dim3(32, 8)>>>(W_in, Winhi, Winlo, FIN, HID, 0);
    {
        const int xn4 = NTYPES * NNODES * FIN / 4;
        split_kernel<<<(xn4 + 255) / 256, 256>>>(x_all, xhi, xlo, xn4);
    }

    // ---- input projection: all 5 types in one batched launch ----
    gemm_mma_b<2,64><<<dim3(gx, 4, NTYPES), 256, MS_TOTAL>>>(
        xhi, xlo, (size_t)NNODES * FIN, TL_ID, Winhi, Winlo, b_in,
        h, nullptr, nullptr, nullptr, nullptr, NNODES);

    // ================= layer 0: active t = {0,1,3,4} =================
    gather_split_kernel<<<dim3(NNODES, 4), 128>>>(h, TL_L0, 0, nullptr, nullptr,
                                                  off, eidx, Ahi, Alo);
    gemm_mma_b<0,512><<<dim3(gx, 4, 4), 256, MS_TOTAL>>>(
        Ahi, Alo, TOFF, TL_L0, W1hi, W1lo, b1,
        nullptr, Mhi, Mlo, nullptr, nullptr, NNODES);
    // GEMM2-L0: t=0 -> relu -> h2[1]; t=3 -> relu -> h2[3]; t=1 -> y1; t=4 -> y4
    gemm_mma_b<1,512><<<dim3(gx, 4, 4), 256, MS_TOTAL>>>(
        Mhi, Mlo, TOFF, TL_L0, W2hi, W2lo, b2,
        h2, nullptr, nullptr, y1, y4, NNODES);

    // ================= layer 1: active t = {1,4}; dst-0 self term from y1+y4 ====
    gather_split_kernel<<<dim3(NNODES, 2), 128>>>(h2, TL_L1, 1, y1, y4,
                                                  off, eidx, Ahi, Alo);
    gemm_mma_b<0,512><<<dim3(gx, 4, 2), 256, MS_TOTAL>>>(
        Ahi, Alo, TOFF, TL_L1, W1hi + (size_t)NET * WOFF, W1lo + (size_t)NET * WOFF,
        b1 + (size_t)NET * HID, nullptr, Mhi, Mlo, nullptr, nullptr, NNODES);
    gemm_mma_b<1,512><<<dim3(gx, 4, 2), 256, MS_TOTAL>>>(
        Mhi, Mlo, TOFF, TL_L1, W2hi + (size_t)NET * WOFF, W2lo + (size_t)NET * WOFF,
        b2 + (size_t)NET * HID, nullptr, nullptr, nullptr, y1, y4, NNODES);

    // ---- fused combine + output head on 'product' nodes ----
    head2_kernel<<<(NNODES * 32 + 255) / 256, 256>>>(y1, y4, W_out, b_out, out, NNODES);
}